// round 1
// baseline (speedup 1.0000x reference)
#include <cuda_runtime.h>

#define N_NODES 100000
#define N_EDGES 1600000
#define N_GRAPH 100
#define IN_DIM 64
#define LATENT 128
#define LN_EPS 1e-5f

// ---------------- scratch (device globals; no allocation allowed) ----------------
__device__ float g_h[(size_t)N_NODES * LATENT];   // node state
__device__ float g_a[(size_t)N_NODES * LATENT];   // scratch A (mlp hidden / agg)
__device__ float g_b[(size_t)N_NODES * LATENT];   // scratch B (mlp out / xs)
__device__ int   g_cs[N_NODES];
__device__ int   g_cr[N_NODES];
__device__ float g_invs[N_NODES];
__device__ float g_invr[N_NODES];

// ---------------- degree kernels ----------------
__global__ void k_zero_deg() {
    int i = blockIdx.x * blockDim.x + threadIdx.x;
    if (i < N_NODES) { g_cs[i] = 0; g_cr[i] = 0; }
}

__global__ void k_count(const int* __restrict__ senders, const int* __restrict__ receivers) {
    int e = blockIdx.x * blockDim.x + threadIdx.x;
    if (e < N_EDGES) {
        atomicAdd(&g_cs[senders[e]], 1);
        atomicAdd(&g_cr[receivers[e]], 1);
    }
}

__global__ void k_inv() {
    int i = blockIdx.x * blockDim.x + threadIdx.x;
    if (i < N_NODES) {
        g_invs[i] = rsqrtf((float)(g_cs[i] + 1));  // +1 for self loop
        g_invr[i] = rsqrtf((float)(g_cr[i] + 1));
    }
}

// ---------------- GEMM: C[M,128] = (relu)(A[M,K] @ W[K,128] + bias) ----------------
// Block: 256 threads, tile 64 rows x 128 cols, each thread 4x8 outputs.
// Full W resident in SMEM; A tile staged with +4 padding for conflict-free column reads.
template<int K, bool RELU>
__global__ __launch_bounds__(256)
void k_gemm(const float* __restrict__ A, const float* __restrict__ W,
            const float* __restrict__ bias, float* __restrict__ C, int M) {
    extern __shared__ float smem[];
    float* sW = smem;                 // [K][128]
    const int AS = K + 4;
    float* sA = smem + K * 128;       // [64][K+4]

    const int tid = threadIdx.x;
    const int row0 = blockIdx.x * 64;

    // stage W (coalesced float4)
    for (int idx = tid * 4; idx < K * 128; idx += 256 * 4) {
        *(float4*)&sW[idx] = *(const float4*)&W[idx];
    }
    // stage A tile
    for (int idx = tid * 4; idx < 64 * K; idx += 256 * 4) {
        int r = idx / K;
        int c = idx - r * K;
        float4 v = make_float4(0.f, 0.f, 0.f, 0.f);
        if (row0 + r < M) v = *(const float4*)&A[(size_t)(row0 + r) * K + c];
        *(float4*)&sA[r * AS + c] = v;
    }
    __syncthreads();

    const int tx = tid & 15;   // 16 col-groups * 8 cols
    const int ty = tid >> 4;   // 16 row-groups * 4 rows

    float acc[4][8];
#pragma unroll
    for (int i = 0; i < 4; i++)
#pragma unroll
        for (int j = 0; j < 8; j++) acc[i][j] = 0.f;

#pragma unroll 4
    for (int k = 0; k < K; k++) {
        float4 b0 = *(const float4*)&sW[k * 128 + tx * 8];
        float4 b1 = *(const float4*)&sW[k * 128 + tx * 8 + 4];
        float a[4];
#pragma unroll
        for (int i = 0; i < 4; i++) a[i] = sA[(ty * 4 + i) * AS + k];
#pragma unroll
        for (int i = 0; i < 4; i++) {
            acc[i][0] += a[i] * b0.x; acc[i][1] += a[i] * b0.y;
            acc[i][2] += a[i] * b0.z; acc[i][3] += a[i] * b0.w;
            acc[i][4] += a[i] * b1.x; acc[i][5] += a[i] * b1.y;
            acc[i][6] += a[i] * b1.z; acc[i][7] += a[i] * b1.w;
        }
    }

    const int cbase = tx * 8;
    float4 bias0 = *(const float4*)&bias[cbase];
    float4 bias1 = *(const float4*)&bias[cbase + 4];
#pragma unroll
    for (int i = 0; i < 4; i++) {
        int r = row0 + ty * 4 + i;
        if (r < M) {
            float4 v0, v1;
            v0.x = acc[i][0] + bias0.x; v0.y = acc[i][1] + bias0.y;
            v0.z = acc[i][2] + bias0.z; v0.w = acc[i][3] + bias0.w;
            v1.x = acc[i][4] + bias1.x; v1.y = acc[i][5] + bias1.y;
            v1.z = acc[i][6] + bias1.z; v1.w = acc[i][7] + bias1.w;
            if (RELU) {
                v0.x = fmaxf(v0.x, 0.f); v0.y = fmaxf(v0.y, 0.f);
                v0.z = fmaxf(v0.z, 0.f); v0.w = fmaxf(v0.w, 0.f);
                v1.x = fmaxf(v1.x, 0.f); v1.y = fmaxf(v1.y, 0.f);
                v1.z = fmaxf(v1.z, 0.f); v1.w = fmaxf(v1.w, 0.f);
            }
            *(float4*)&C[(size_t)r * 128 + cbase] = v0;
            *(float4*)&C[(size_t)r * 128 + cbase + 4] = v1;
        }
    }
}

// ---------------- scale by inv_sqrt_sdeg (in place) + init agg with self-loop ----------------
__global__ __launch_bounds__(256)
void k_scale(float* __restrict__ x, float* __restrict__ agg) {
    int idx = blockIdx.x * blockDim.x + threadIdx.x;   // float4 index
    if (idx < N_NODES * (LATENT / 4)) {
        int row = idx >> 5;                            // 32 float4 per row
        float s = g_invs[row];
        float4 v = ((float4*)x)[idx];
        v.x *= s; v.y *= s; v.z *= s; v.w *= s;
        ((float4*)x)[idx] = v;
        ((float4*)agg)[idx] = v;                       // self-loop contribution
    }
}

// ---------------- edge aggregation: one warp per edge, vector red ----------------
__global__ __launch_bounds__(256)
void k_edge(const int* __restrict__ senders, const int* __restrict__ receivers,
            const float* __restrict__ xs, float* __restrict__ agg) {
    int warp = (blockIdx.x * blockDim.x + threadIdx.x) >> 5;
    int lane = threadIdx.x & 31;
    if (warp < N_EDGES) {
        int s = senders[warp];
        int r = receivers[warp];
        float4 v = *(const float4*)&xs[(size_t)s * 128 + lane * 4];
        float* dst = &agg[(size_t)r * 128 + lane * 4];
        asm volatile("red.global.add.v4.f32 [%0], {%1, %2, %3, %4};"
                     :: "l"(dst), "f"(v.x), "f"(v.y), "f"(v.z), "f"(v.w)
                     : "memory");
    }
}

// ---------------- h = LayerNorm(agg * inv_r + h): one warp per row ----------------
__global__ __launch_bounds__(256)
void k_ln(const float* __restrict__ agg, float* __restrict__ h,
          const float* __restrict__ scale, const float* __restrict__ offset) {
    int row = (blockIdx.x * blockDim.x + threadIdx.x) >> 5;
    int lane = threadIdx.x & 31;
    if (row >= N_NODES) return;
    float ir = g_invr[row];
    int c = lane * 4;
    float4 va = *(const float4*)&agg[(size_t)row * 128 + c];
    float4 vh = *(const float4*)&h[(size_t)row * 128 + c];
    float4 y;
    y.x = va.x * ir + vh.x; y.y = va.y * ir + vh.y;
    y.z = va.z * ir + vh.z; y.w = va.w * ir + vh.w;
    float sum = y.x + y.y + y.z + y.w;
    float sq  = y.x * y.x + y.y * y.y + y.z * y.z + y.w * y.w;
#pragma unroll
    for (int o = 16; o; o >>= 1) {
        sum += __shfl_xor_sync(0xffffffffu, sum, o);
        sq  += __shfl_xor_sync(0xffffffffu, sq, o);
    }
    float mean = sum * (1.f / 128.f);
    float var  = sq * (1.f / 128.f) - mean * mean;
    float rs = rsqrtf(var + LN_EPS);
    float4 sc = *(const float4*)&scale[c];
    float4 of = *(const float4*)&offset[c];
    y.x = (y.x - mean) * rs * sc.x + of.x;
    y.y = (y.y - mean) * rs * sc.y + of.y;
    y.z = (y.z - mean) * rs * sc.z + of.z;
    y.w = (y.w - mean) * rs * sc.w + of.w;
    *(float4*)&h[(size_t)row * 128 + c] = y;
}

// ---------------- pool (segment mean over contiguous 1000-node graphs) + decode ----------------
__global__ __launch_bounds__(128)
void k_pool(const float* __restrict__ dec_w, const float* __restrict__ dec_b,
            float* __restrict__ out) {
    int g = blockIdx.x;
    int c = threadIdx.x;
    const int per = N_NODES / N_GRAPH;  // 1000
    const float* base = g_h + (size_t)g * per * 128;
    float sum = 0.f;
#pragma unroll 8
    for (int r = 0; r < per; r++) sum += base[(size_t)r * 128 + c];
    float val = (sum * (1.f / (float)per)) * dec_w[c];
    __shared__ float red[4];
#pragma unroll
    for (int o = 16; o; o >>= 1) val += __shfl_xor_sync(0xffffffffu, val, o);
    if ((threadIdx.x & 31) == 0) red[threadIdx.x >> 5] = val;
    __syncthreads();
    if (threadIdx.x == 0) out[g] = red[0] + red[1] + red[2] + red[3] + dec_b[0];
}

// ---------------- launch ----------------
extern "C" void kernel_launch(void* const* d_in, const int* in_sizes, int n_in,
                              void* d_out, int out_size) {
    const float* nodes     = (const float*)d_in[0];
    const int*   senders   = (const int*)d_in[1];
    const int*   receivers = (const int*)d_in[2];
    // d_in[3] = graph_ids (contiguous blocks of 1000; not needed)
    const float* embed_w   = (const float*)d_in[4];
    const float* embed_b   = (const float*)d_in[5];
    const float* mlp_w     = (const float*)d_in[6];
    const float* mlp_b     = (const float*)d_in[7];
    const float* ln_scale  = (const float*)d_in[8];
    const float* ln_offset = (const float*)d_in[9];
    const float* dec_w     = (const float*)d_in[10];
    const float* dec_b     = (const float*)d_in[11];
    float* out = (float*)d_out;

    float *ph, *pa, *pb;
    cudaGetSymbolAddress((void**)&ph, g_h);
    cudaGetSymbolAddress((void**)&pa, g_a);
    cudaGetSymbolAddress((void**)&pb, g_b);

    const int smem64  = (64 * 128 + 64 * (64 + 4)) * 4;    // 50176 B
    const int smem128 = (128 * 128 + 64 * (128 + 4)) * 4;  // 99328 B
    cudaFuncSetAttribute(k_gemm<64, false>, cudaFuncAttributeMaxDynamicSharedMemorySize, smem64);
    cudaFuncSetAttribute(k_gemm<128, true>, cudaFuncAttributeMaxDynamicSharedMemorySize, smem128);

    // degrees
    k_zero_deg<<<(N_NODES + 255) / 256, 256>>>();
    k_count<<<(N_EDGES + 255) / 256, 256>>>(senders, receivers);
    k_inv<<<(N_NODES + 255) / 256, 256>>>();

    const int gemm_grid = (N_NODES + 63) / 64;

    // embed: h = nodes @ embed_w + embed_b
    k_gemm<64, false><<<gemm_grid, 256, smem64>>>(nodes, embed_w, embed_b, ph, N_NODES);

    const int elem_grid = (N_NODES * (LATENT / 4) + 255) / 256;   // float4-elem kernels
    const int row_grid  = (N_NODES * 32 + 255) / 256;             // warp-per-row kernels
    const int edge_grid = (N_EDGES * 32 + 255) / 256;             // warp-per-edge

    for (int s = 0; s < 2; s++) {
        const float* W0 = mlp_w + (size_t)(s * 2 + 0) * LATENT * LATENT;
        const float* W1 = mlp_w + (size_t)(s * 2 + 1) * LATENT * LATENT;
        const float* b0 = mlp_b + (size_t)(s * 2 + 0) * LATENT;
        const float* b1 = mlp_b + (size_t)(s * 2 + 1) * LATENT;

        k_gemm<128, true><<<gemm_grid, 256, smem128>>>(ph, W0, b0, pa, N_NODES);
        k_gemm<128, true><<<gemm_grid, 256, smem128>>>(pa, W1, b1, pb, N_NODES);

        // xs = x * inv_sqrt_sdeg (in place in pb); agg(pa) = xs (self loop)
        k_scale<<<elem_grid, 256>>>(pb, pa);
        // agg[r] += xs[s] for all edges
        k_edge<<<edge_grid, 256>>>(senders, receivers, pb, pa);
        // h = LN(agg * inv_sqrt_rdeg + h)
        k_ln<<<row_grid, 256>>>(pa, ph, ln_scale + s * LATENT, ln_offset + s * LATENT);
    }

    k_pool<<<N_GRAPH, 128>>>(dec_w, dec_b, out);
}

// round 3
// speedup vs baseline: 1.3859x; 1.3859x over previous
#include <cuda_runtime.h>
#include <cstdint>

#define N_NODES 100000
#define N_EDGES 1600000
#define N_GRAPH 100
#define IN_DIM 64
#define LATENT 128
#define LN_EPS 1e-5f

// ---------------- scratch (device globals; no allocation allowed) ----------------
__device__ float g_h[(size_t)N_NODES * LATENT];   // node state
__device__ float g_a[(size_t)N_NODES * LATENT];   // scratch A (mlp hidden / agg)
__device__ float g_b[(size_t)N_NODES * LATENT];   // scratch B (mlp out / xs)
__device__ int   g_cs[N_NODES];
__device__ int   g_cr[N_NODES];
__device__ float g_invs[N_NODES];
__device__ float g_invr[N_NODES];

// ---------------- degree kernels ----------------
__global__ void k_zero_deg() {
    int i = blockIdx.x * blockDim.x + threadIdx.x;
    if (i < N_NODES) { g_cs[i] = 0; g_cr[i] = 0; }
}
__global__ void k_count(const int* __restrict__ senders, const int* __restrict__ receivers) {
    int e = blockIdx.x * blockDim.x + threadIdx.x;
    if (e < N_EDGES) {
        atomicAdd(&g_cs[senders[e]], 1);
        atomicAdd(&g_cr[receivers[e]], 1);
    }
}
__global__ void k_inv() {
    int i = blockIdx.x * blockDim.x + threadIdx.x;
    if (i < N_NODES) {
        g_invs[i] = rsqrtf((float)(g_cs[i] + 1));
        g_invr[i] = rsqrtf((float)(g_cr[i] + 1));
    }
}

// ---------------- tf32 helpers (portable PTX, no sm_103a-only instructions) ----------------
__device__ __forceinline__ uint32_t f2tf32(float x) {
    uint32_t r;
    asm("cvt.rna.tf32.f32 %0, %1;" : "=r"(r) : "f"(x));
    return r;
}
__device__ __forceinline__ void mma_tf32(float c[4], const uint32_t a[4], const uint32_t b[2]) {
    asm volatile(
        "mma.sync.aligned.m16n8k8.row.col.f32.tf32.tf32.f32 "
        "{%0,%1,%2,%3}, {%4,%5,%6,%7}, {%8,%9}, {%0,%1,%2,%3};"
        : "+f"(c[0]), "+f"(c[1]), "+f"(c[2]), "+f"(c[3])
        : "r"(a[0]), "r"(a[1]), "r"(a[2]), "r"(a[3]),
          "r"(b[0]), "r"(b[1]));
}

// ---------------- warp-MMA tf32 GEMM, hi/lo split (~fp32 accuracy) ----------------
// C[M,128] = epilogue(A[M,KTOT] @ W[KTOT,128] + bias)
// MODE 0: +bias   MODE 1: +bias,relu   MODE 2: +bias,relu, *g_invs[row], dual-write C,C2
// Block 512 thr = 16 warps, CTA tile 128x128, warp tile 32x32 (2 m-frags x 4 n-frags),
// K chunked by 64. SMEM tiles stride 68 floats: fragment LDS bank = (4*row + col)%32,
// conflict-free for the 8x4 (group,tig) access pattern.
#define STR 68
#define TILE_U32 (128 * STR)

template<int KTOT, int MODE>
__global__ __launch_bounds__(512)
void k_gemm_mma(const float* __restrict__ A, const float* __restrict__ W,
                const float* __restrict__ bias, float* __restrict__ C,
                float* __restrict__ C2, int M) {
    extern __shared__ uint32_t sm[];
    uint32_t* sAhi = sm;
    uint32_t* sAlo = sAhi + TILE_U32;
    uint32_t* sBhi = sAlo + TILE_U32;
    uint32_t* sBlo = sBhi + TILE_U32;
    float*    sBias = (float*)(sBlo + TILE_U32);

    const int tid  = threadIdx.x;
    const int lane = tid & 31;
    const int wid  = tid >> 5;
    const int grp  = lane >> 2;   // 0..7
    const int tig  = lane & 3;    // 0..3
    const int wm   = wid & 3;     // warp row 0..3  (32 rows each)
    const int wn   = wid >> 2;    // warp col 0..3  (32 cols each)
    const int row0 = blockIdx.x * 128;

    if (tid < 128) sBias[tid] = bias[tid];

    float acc[2][4][4];
#pragma unroll
    for (int i = 0; i < 2; i++)
#pragma unroll
        for (int j = 0; j < 4; j++)
#pragma unroll
            for (int q = 0; q < 4; q++) acc[i][j][q] = 0.f;

    const int n_chunks = KTOT / 64;
    for (int ch = 0; ch < n_chunks; ch++) {
        if (ch) __syncthreads();
        // ---- stage A chunk [128 rows x 64 k] as tf32 hi/lo (float4 loads) ----
#pragma unroll
        for (int it = 0; it < 4; it++) {
            int i  = tid + it * 512;          // 2048 float4 total
            int r  = i >> 4;
            int c4 = (i & 15) * 4;
            float4 v = make_float4(0.f, 0.f, 0.f, 0.f);
            if (row0 + r < M)
                v = *(const float4*)&A[(size_t)(row0 + r) * KTOT + ch * 64 + c4];
            uint32_t h0 = f2tf32(v.x), h1 = f2tf32(v.y), h2 = f2tf32(v.z), h3 = f2tf32(v.w);
            uint32_t l0 = f2tf32(v.x - __uint_as_float(h0));
            uint32_t l1 = f2tf32(v.y - __uint_as_float(h1));
            uint32_t l2 = f2tf32(v.z - __uint_as_float(h2));
            uint32_t l3 = f2tf32(v.w - __uint_as_float(h3));
            uint32_t* ph = &sAhi[r * STR + c4];
            uint32_t* pl = &sAlo[r * STR + c4];
            *(uint4*)ph = make_uint4(h0, h1, h2, h3);
            *(uint4*)pl = make_uint4(l0, l1, l2, l3);
        }
        // ---- stage B chunk = W^T: sB[n][k] from W[k][n] ----
#pragma unroll
        for (int it = 0; it < 16; it++) {
            int i = tid + it * 512;           // 8192 elems
            int k = i >> 7, n = i & 127;
            float v = __ldg(&W[(size_t)(ch * 64 + k) * 128 + n]);
            uint32_t h = f2tf32(v);
            uint32_t l = f2tf32(v - __uint_as_float(h));
            sBhi[n * STR + k] = h;
            sBlo[n * STR + k] = l;
        }
        __syncthreads();

        // ---- compute: 8 k-steps of 8 ----
#pragma unroll 2
        for (int ks = 0; ks < 8; ks++) {
            const int k0 = ks * 8;
            uint32_t aH[2][4], aL[2][4];
#pragma unroll
            for (int mt = 0; mt < 2; mt++) {
                int base = (wm * 32 + mt * 16 + grp) * STR + k0 + tig;
                aH[mt][0] = sAhi[base];
                aH[mt][1] = sAhi[base + 8 * STR];
                aH[mt][2] = sAhi[base + 4];
                aH[mt][3] = sAhi[base + 8 * STR + 4];
                aL[mt][0] = sAlo[base];
                aL[mt][1] = sAlo[base + 8 * STR];
                aL[mt][2] = sAlo[base + 4];
                aL[mt][3] = sAlo[base + 8 * STR + 4];
            }
            uint32_t bH[4][2], bL[4][2];
#pragma unroll
            for (int nt = 0; nt < 4; nt++) {
                int base = (wn * 32 + nt * 8 + grp) * STR + k0 + tig;
                bH[nt][0] = sBhi[base];
                bH[nt][1] = sBhi[base + 4];
                bL[nt][0] = sBlo[base];
                bL[nt][1] = sBlo[base + 4];
            }
#pragma unroll
            for (int mt = 0; mt < 2; mt++)
#pragma unroll
                for (int nt = 0; nt < 4; nt++) {
                    mma_tf32(acc[mt][nt], aH[mt], bH[nt]);
                    mma_tf32(acc[mt][nt], aH[mt], bL[nt]);
                    mma_tf32(acc[mt][nt], aL[mt], bH[nt]);
                }
        }
    }

    // ---- epilogue ----
#pragma unroll
    for (int mt = 0; mt < 2; mt++) {
        int ra = row0 + wm * 32 + mt * 16 + grp;     // rows for c0/c1
        int rb = ra + 8;                             // rows for c2/c3
        float sa = 1.f, sb = 1.f;
        if (MODE == 2) {
            if (ra < M) sa = g_invs[ra];
            if (rb < M) sb = g_invs[rb];
        }
#pragma unroll
        for (int nt = 0; nt < 4; nt++) {
            int col = wn * 32 + nt * 8 + 2 * tig;
            float b0 = sBias[col], b1 = sBias[col + 1];
            float v0 = acc[mt][nt][0] + b0;
            float v1 = acc[mt][nt][1] + b1;
            float v2 = acc[mt][nt][2] + b0;
            float v3 = acc[mt][nt][3] + b1;
            if (MODE >= 1) {
                v0 = fmaxf(v0, 0.f); v1 = fmaxf(v1, 0.f);
                v2 = fmaxf(v2, 0.f); v3 = fmaxf(v3, 0.f);
            }
            if (MODE == 2) { v0 *= sa; v1 *= sa; v2 *= sb; v3 *= sb; }
            if (ra < M) {
                float2 p = make_float2(v0, v1);
                *(float2*)&C[(size_t)ra * 128 + col] = p;
                if (MODE == 2) *(float2*)&C2[(size_t)ra * 128 + col] = p;
            }
            if (rb < M) {
                float2 p = make_float2(v2, v3);
                *(float2*)&C[(size_t)rb * 128 + col] = p;
                if (MODE == 2) *(float2*)&C2[(size_t)rb * 128 + col] = p;
            }
        }
    }
}

#define SM_GEMM_TOTAL (4 * TILE_U32 * 4 + 128 * 4)   // 139264 + 512 bytes

// ---------------- edge aggregation: one warp per edge, vector red ----------------
__global__ __launch_bounds__(256)
void k_edge(const int* __restrict__ senders, const int* __restrict__ receivers,
            const float* __restrict__ xs, float* __restrict__ agg) {
    int warp = (blockIdx.x * blockDim.x + threadIdx.x) >> 5;
    int lane = threadIdx.x & 31;
    if (warp < N_EDGES) {
        int s = senders[warp];
        int r = receivers[warp];
        float4 v = *(const float4*)&xs[(size_t)s * 128 + lane * 4];
        float* dst = &agg[(size_t)r * 128 + lane * 4];
        asm volatile("red.global.add.v4.f32 [%0], {%1, %2, %3, %4};"
                     :: "l"(dst), "f"(v.x), "f"(v.y), "f"(v.z), "f"(v.w)
                     : "memory");
    }
}

// ---------------- h = LayerNorm(agg * inv_r + h): one warp per row ----------------
__global__ __launch_bounds__(256)
void k_ln(const float* __restrict__ agg, float* __restrict__ h,
          const float* __restrict__ scale, const float* __restrict__ offset) {
    int row = (blockIdx.x * blockDim.x + threadIdx.x) >> 5;
    int lane = threadIdx.x & 31;
    if (row >= N_NODES) return;
    float ir = g_invr[row];
    int c = lane * 4;
    float4 va = *(const float4*)&agg[(size_t)row * 128 + c];
    float4 vh = *(const float4*)&h[(size_t)row * 128 + c];
    float4 y;
    y.x = va.x * ir + vh.x; y.y = va.y * ir + vh.y;
    y.z = va.z * ir + vh.z; y.w = va.w * ir + vh.w;
    float sum = y.x + y.y + y.z + y.w;
    float sq  = y.x * y.x + y.y * y.y + y.z * y.z + y.w * y.w;
#pragma unroll
    for (int o = 16; o; o >>= 1) {
        sum += __shfl_xor_sync(0xffffffffu, sum, o);
        sq  += __shfl_xor_sync(0xffffffffu, sq, o);
    }
    float mean = sum * (1.f / 128.f);
    float var  = sq * (1.f / 128.f) - mean * mean;
    float rs = rsqrtf(var + LN_EPS);
    float4 scv = *(const float4*)&scale[c];
    float4 ofv = *(const float4*)&offset[c];
    y.x = (y.x - mean) * rs * scv.x + ofv.x;
    y.y = (y.y - mean) * rs * scv.y + ofv.y;
    y.z = (y.z - mean) * rs * scv.z + ofv.z;
    y.w = (y.w - mean) * rs * scv.w + ofv.w;
    *(float4*)&h[(size_t)row * 128 + c] = y;
}

// ---------------- pool (segment mean, contiguous 1000-node graphs) + decode ----------------
__global__ __launch_bounds__(128)
void k_pool(const float* __restrict__ dec_w, const float* __restrict__ dec_b,
            float* __restrict__ out) {
    int g = blockIdx.x;
    int c = threadIdx.x;
    const int per = N_NODES / N_GRAPH;  // 1000
    const float* base = g_h + (size_t)g * per * 128;
    float sum = 0.f;
#pragma unroll 8
    for (int r = 0; r < per; r++) sum += base[(size_t)r * 128 + c];
    float val = (sum * (1.f / (float)per)) * dec_w[c];
    __shared__ float red[4];
#pragma unroll
    for (int o = 16; o; o >>= 1) val += __shfl_xor_sync(0xffffffffu, val, o);
    if ((threadIdx.x & 31) == 0) red[threadIdx.x >> 5] = val;
    __syncthreads();
    if (threadIdx.x == 0) out[g] = red[0] + red[1] + red[2] + red[3] + dec_b[0];
}

// ---------------- launch ----------------
extern "C" void kernel_launch(void* const* d_in, const int* in_sizes, int n_in,
                              void* d_out, int out_size) {
    const float* nodes     = (const float*)d_in[0];
    const int*   senders   = (const int*)d_in[1];
    const int*   receivers = (const int*)d_in[2];
    // d_in[3] = graph_ids (contiguous blocks of 1000; not needed)
    const float* embed_w   = (const float*)d_in[4];
    const float* embed_b   = (const float*)d_in[5];
    const float* mlp_w     = (const float*)d_in[6];
    const float* mlp_b     = (const float*)d_in[7];
    const float* ln_scale  = (const float*)d_in[8];
    const float* ln_offset = (const float*)d_in[9];
    const float* dec_w     = (const float*)d_in[10];
    const float* dec_b     = (const float*)d_in[11];
    float* out = (float*)d_out;

    float *ph, *pa, *pb;
    cudaGetSymbolAddress((void**)&ph, g_h);
    cudaGetSymbolAddress((void**)&pa, g_a);
    cudaGetSymbolAddress((void**)&pb, g_b);

    cudaFuncSetAttribute(k_gemm_mma<64, 0>,  cudaFuncAttributeMaxDynamicSharedMemorySize, SM_GEMM_TOTAL);
    cudaFuncSetAttribute(k_gemm_mma<128, 1>, cudaFuncAttributeMaxDynamicSharedMemorySize, SM_GEMM_TOTAL);
    cudaFuncSetAttribute(k_gemm_mma<128, 2>, cudaFuncAttributeMaxDynamicSharedMemorySize, SM_GEMM_TOTAL);

    // degrees
    k_zero_deg<<<(N_NODES + 255) / 256, 256>>>();
    k_count<<<(N_EDGES + 255) / 256, 256>>>(senders, receivers);
    k_inv<<<(N_NODES + 255) / 256, 256>>>();

    const int gemm_grid = (N_NODES + 127) / 128;   // 782

    // embed: h = nodes @ embed_w + embed_b
    k_gemm_mma<64, 0><<<gemm_grid, 512, SM_GEMM_TOTAL>>>(nodes, embed_w, embed_b, ph, nullptr, N_NODES);

    const int row_grid  = (N_NODES * 32 + 255) / 256;   // warp-per-row
    const int edge_grid = (N_EDGES * 32 + 255) / 256;   // warp-per-edge

    for (int s = 0; s < 2; s++) {
        const float* W0 = mlp_w + (size_t)(s * 2 + 0) * LATENT * LATENT;
        const float* W1 = mlp_w + (size_t)(s * 2 + 1) * LATENT * LATENT;
        const float* b0 = mlp_b + (size_t)(s * 2 + 0) * LATENT;
        const float* b1 = mlp_b + (size_t)(s * 2 + 1) * LATENT;

        // hidden = relu(h @ W0 + b0)
        k_gemm_mma<128, 1><<<gemm_grid, 512, SM_GEMM_TOTAL>>>(ph, W0, b0, pa, nullptr, N_NODES);
        // xs (pb) = relu(hidden @ W1 + b1) * inv_sqrt_sdeg; agg (pa) = xs (self-loop)
        k_gemm_mma<128, 2><<<gemm_grid, 512, SM_GEMM_TOTAL>>>(pa, W1, b1, pb, pa, N_NODES);
        // agg[r] += xs[s]
        k_edge<<<edge_grid, 256>>>(senders, receivers, pb, pa);
        // h = LN(agg * inv_sqrt_rdeg + h)
        k_ln<<<row_grid, 256>>>(pa, ph, ln_scale + s * LATENT, ln_offset + s * LATENT);
    }

    k_pool<<<N_GRAPH, 128>>>(dec_w, dec_b, out);
}

// round 4
// speedup vs baseline: 1.6973x; 1.2247x over previous
#include <cuda_runtime.h>
#include <cuda_fp16.h>
#include <cstdint>

#define N_NODES 100000
#define N_EDGES 1600000
#define N_GRAPH 100
#define IN_DIM 64
#define LATENT 128
#define LN_EPS 1e-5f

// ---------------- scratch (device globals; no allocation allowed) ----------------
__device__ float g_h[(size_t)N_NODES * LATENT];   // node state
__device__ float g_a[(size_t)N_NODES * LATENT];   // scratch A (mlp hidden / agg)
__device__ float g_b[(size_t)N_NODES * LATENT];   // scratch B (mlp out / xs)
__device__ int   g_cs[N_NODES];
__device__ int   g_cr[N_NODES];
__device__ float g_invs[N_NODES];
__device__ float g_invr[N_NODES];

// ---------------- degree kernels ----------------
__global__ void k_zero_deg() {
    int i = blockIdx.x * blockDim.x + threadIdx.x;
    if (i < N_NODES) { g_cs[i] = 0; g_cr[i] = 0; }
}
__global__ void k_count(const int* __restrict__ senders, const int* __restrict__ receivers) {
    int e = blockIdx.x * blockDim.x + threadIdx.x;
    if (e < N_EDGES) {
        atomicAdd(&g_cs[senders[e]], 1);
        atomicAdd(&g_cr[receivers[e]], 1);
    }
}
__global__ void k_inv() {
    int i = blockIdx.x * blockDim.x + threadIdx.x;
    if (i < N_NODES) {
        g_invs[i] = rsqrtf((float)(g_cs[i] + 1));
        g_invr[i] = rsqrtf((float)(g_cr[i] + 1));
    }
}

// ---------------- fp16 helpers ----------------
__device__ __forceinline__ void hilo(float x, __half& h, float& res) {
    h = __float2half_rn(x);
    res = x - __half2float(h);
}
__device__ __forceinline__ uint32_t pack2(__half a, __half b) {
    __half2 h = __halves2half2(a, b);
    return *(uint32_t*)&h;
}
__device__ __forceinline__ void mma_f16(float c[4], const uint32_t a[4],
                                        uint32_t b0, uint32_t b1) {
    asm volatile(
        "mma.sync.aligned.m16n8k16.row.col.f32.f16.f16.f32 "
        "{%0,%1,%2,%3}, {%4,%5,%6,%7}, {%8,%9}, {%0,%1,%2,%3};"
        : "+f"(c[0]), "+f"(c[1]), "+f"(c[2]), "+f"(c[3])
        : "r"(a[0]), "r"(a[1]), "r"(a[2]), "r"(a[3]),
          "r"(b0), "r"(b1));
}

// ---------------- warp-MMA fp16 GEMM, hi/lo split (~fp32 accuracy) ----------------
// C[M,128] = epilogue(A[M,KTOT] @ W[KTOT,128] + bias)
// MODE 0: +bias   MODE 1: +bias,relu   MODE 2: +bias,relu, *g_invs[row], dual-write C,C2
// Block 512 thr = 16 warps, CTA tile 128x128, warp tile 32x32, K chunked by 64.
// SMEM: half2-packed tiles, word stride 36 (32 kpairs + 4 pad) -> fragment LDS
// bank = (4*row + tig)%32, conflict-free. 74KB smem -> 2 CTAs/SM.
#define S2 36
#define TILEW (128 * S2)   // 4608 words per buffer

template<int KTOT, int MODE>
__global__ __launch_bounds__(512, 2)
void k_gemm_h2(const float* __restrict__ A, const float* __restrict__ W,
               const float* __restrict__ bias, float* __restrict__ C,
               float* __restrict__ C2, int M) {
    extern __shared__ uint32_t sm[];
    uint32_t* sAhi = sm;
    uint32_t* sAlo = sAhi + TILEW;
    uint32_t* sBhi = sAlo + TILEW;
    uint32_t* sBlo = sBhi + TILEW;
    float*    sBias = (float*)(sBlo + TILEW);

    const int tid  = threadIdx.x;
    const int lane = tid & 31;
    const int wid  = tid >> 5;
    const int grp  = lane >> 2;   // 0..7
    const int tig  = lane & 3;    // 0..3
    const int wm   = wid & 3;     // warp row (32 rows each)
    const int wn   = wid >> 2;    // warp col (32 cols each)
    const int row0 = blockIdx.x * 128;

    if (tid < 128) sBias[tid] = bias[tid];

    float acc[2][4][4];
#pragma unroll
    for (int i = 0; i < 2; i++)
#pragma unroll
        for (int j = 0; j < 4; j++)
#pragma unroll
            for (int q = 0; q < 4; q++) acc[i][j][q] = 0.f;

    const int n_chunks = KTOT / 64;
    for (int ch = 0; ch < n_chunks; ch++) {
        if (ch) __syncthreads();
        // ---- stage A chunk [128 rows x 64 k] as fp16 hi/lo (float4 loads) ----
#pragma unroll
        for (int it = 0; it < 4; it++) {
            int i  = tid + it * 512;          // 2048 float4 total
            int r  = i >> 4;
            int c4 = (i & 15) * 4;
            float4 v = make_float4(0.f, 0.f, 0.f, 0.f);
            if (row0 + r < M)
                v = *(const float4*)&A[(size_t)(row0 + r) * KTOT + ch * 64 + c4];
            __half h0, h1, h2, h3; float r0, r1, r2, r3;
            hilo(v.x, h0, r0); hilo(v.y, h1, r1);
            hilo(v.z, h2, r2); hilo(v.w, h3, r3);
            int w = r * S2 + (c4 >> 1);
            *(uint2*)&sAhi[w] = make_uint2(pack2(h0, h1), pack2(h2, h3));
            *(uint2*)&sAlo[w] = make_uint2(
                pack2(__float2half_rn(r0), __float2half_rn(r1)),
                pack2(__float2half_rn(r2), __float2half_rn(r3)));
        }
        // ---- stage B chunk = W^T packed by k-pairs: sB[n][kp] from W[k][n] ----
#pragma unroll
        for (int it = 0; it < 8; it++) {
            int i  = tid + it * 512;          // 4096 words total
            int n  = i & 127;
            int kp = i >> 7;                  // 0..31
            const float* wp = &W[(size_t)(ch * 64 + 2 * kp) * 128 + n];
            float v0 = __ldg(wp), v1 = __ldg(wp + 128);
            __half h0, h1; float r0, r1;
            hilo(v0, h0, r0); hilo(v1, h1, r1);
            sBhi[n * S2 + kp] = pack2(h0, h1);
            sBlo[n * S2 + kp] = pack2(__float2half_rn(r0), __float2half_rn(r1));
        }
        __syncthreads();

        // ---- compute: 4 k-steps of 16 ----
#pragma unroll
        for (int ks = 0; ks < 4; ks++) {
            const int kb = ks * 8;
            uint32_t aH[2][4], aL[2][4];
#pragma unroll
            for (int mt = 0; mt < 2; mt++) {
                int base = (wm * 32 + mt * 16 + grp) * S2 + kb + tig;
                aH[mt][0] = sAhi[base];
                aH[mt][1] = sAhi[base + 8 * S2];
                aH[mt][2] = sAhi[base + 4];
                aH[mt][3] = sAhi[base + 8 * S2 + 4];
                aL[mt][0] = sAlo[base];
                aL[mt][1] = sAlo[base + 8 * S2];
                aL[mt][2] = sAlo[base + 4];
                aL[mt][3] = sAlo[base + 8 * S2 + 4];
            }
#pragma unroll
            for (int nt = 0; nt < 4; nt++) {
                int bb = (wn * 32 + nt * 8 + grp) * S2 + kb + tig;
                uint32_t bh0 = sBhi[bb], bh1 = sBhi[bb + 4];
                uint32_t bl0 = sBlo[bb], bl1 = sBlo[bb + 4];
#pragma unroll
                for (int mt = 0; mt < 2; mt++) {
                    mma_f16(acc[mt][nt], aH[mt], bh0, bh1);
                    mma_f16(acc[mt][nt], aH[mt], bl0, bl1);
                    mma_f16(acc[mt][nt], aL[mt], bh0, bh1);
                }
            }
        }
    }

    // ---- epilogue (c0,c1 -> row grp; c2,c3 -> row grp+8; cols 2tig,2tig+1) ----
#pragma unroll
    for (int mt = 0; mt < 2; mt++) {
        int ra = row0 + wm * 32 + mt * 16 + grp;
        int rb = ra + 8;
        float sa = 1.f, sb = 1.f;
        if (MODE == 2) {
            if (ra < M) sa = g_invs[ra];
            if (rb < M) sb = g_invs[rb];
        }
#pragma unroll
        for (int nt = 0; nt < 4; nt++) {
            int col = wn * 32 + nt * 8 + 2 * tig;
            float b0 = sBias[col], b1 = sBias[col + 1];
            float v0 = acc[mt][nt][0] + b0;
            float v1 = acc[mt][nt][1] + b1;
            float v2 = acc[mt][nt][2] + b0;
            float v3 = acc[mt][nt][3] + b1;
            if (MODE >= 1) {
                v0 = fmaxf(v0, 0.f); v1 = fmaxf(v1, 0.f);
                v2 = fmaxf(v2, 0.f); v3 = fmaxf(v3, 0.f);
            }
            if (MODE == 2) { v0 *= sa; v1 *= sa; v2 *= sb; v3 *= sb; }
            if (ra < M) {
                float2 p = make_float2(v0, v1);
                *(float2*)&C[(size_t)ra * 128 + col] = p;
                if (MODE == 2) *(float2*)&C2[(size_t)ra * 128 + col] = p;
            }
            if (rb < M) {
                float2 p = make_float2(v2, v3);
                *(float2*)&C[(size_t)rb * 128 + col] = p;
                if (MODE == 2) *(float2*)&C2[(size_t)rb * 128 + col] = p;
            }
        }
    }
}

#define SM_GEMM_TOTAL (4 * TILEW * 4 + 128 * 4)   // 73728 + 512 bytes

// ---------------- edge aggregation: one warp per edge, vector red ----------------
__global__ __launch_bounds__(256)
void k_edge(const int* __restrict__ senders, const int* __restrict__ receivers,
            const float* __restrict__ xs, float* __restrict__ agg) {
    int warp = (blockIdx.x * blockDim.x + threadIdx.x) >> 5;
    int lane = threadIdx.x & 31;
    if (warp < N_EDGES) {
        int s = senders[warp];
        int r = receivers[warp];
        float4 v = *(const float4*)&xs[(size_t)s * 128 + lane * 4];
        float* dst = &agg[(size_t)r * 128 + lane * 4];
        asm volatile("red.global.add.v4.f32 [%0], {%1, %2, %3, %4};"
                     :: "l"(dst), "f"(v.x), "f"(v.y), "f"(v.z), "f"(v.w)
                     : "memory");
    }
}

// ---------------- h = LayerNorm(agg * inv_r + h): one warp per row ----------------
__global__ __launch_bounds__(256)
void k_ln(const float* __restrict__ agg, float* __restrict__ h,
          const float* __restrict__ scale, const float* __restrict__ offset) {
    int row = (blockIdx.x * blockDim.x + threadIdx.x) >> 5;
    int lane = threadIdx.x & 31;
    if (row >= N_NODES) return;
    float ir = g_invr[row];
    int c = lane * 4;
    float4 va = *(const float4*)&agg[(size_t)row * 128 + c];
    float4 vh = *(const float4*)&h[(size_t)row * 128 + c];
    float4 y;
    y.x = va.x * ir + vh.x; y.y = va.y * ir + vh.y;
    y.z = va.z * ir + vh.z; y.w = va.w * ir + vh.w;
    float sum = y.x + y.y + y.z + y.w;
    float sq  = y.x * y.x + y.y * y.y + y.z * y.z + y.w * y.w;
#pragma unroll
    for (int o = 16; o; o >>= 1) {
        sum += __shfl_xor_sync(0xffffffffu, sum, o);
        sq  += __shfl_xor_sync(0xffffffffu, sq, o);
    }
    float mean = sum * (1.f / 128.f);
    float var  = sq * (1.f / 128.f) - mean * mean;
    float rs = rsqrtf(var + LN_EPS);
    float4 scv = *(const float4*)&scale[c];
    float4 ofv = *(const float4*)&offset[c];
    y.x = (y.x - mean) * rs * scv.x + ofv.x;
    y.y = (y.y - mean) * rs * scv.y + ofv.y;
    y.z = (y.z - mean) * rs * scv.z + ofv.z;
    y.w = (y.w - mean) * rs * scv.w + ofv.w;
    *(float4*)&h[(size_t)row * 128 + c] = y;
}

// ---------------- pool (segment mean, contiguous 1000-node graphs) + decode ----------------
__global__ __launch_bounds__(128)
void k_pool(const float* __restrict__ dec_w, const float* __restrict__ dec_b,
            float* __restrict__ out) {
    int g = blockIdx.x;
    int c = threadIdx.x;
    const int per = N_NODES / N_GRAPH;  // 1000
    const float* base = g_h + (size_t)g * per * 128;
    float sum = 0.f;
#pragma unroll 8
    for (int r = 0; r < per; r++) sum += base[(size_t)r * 128 + c];
    float val = (sum * (1.f / (float)per)) * dec_w[c];
    __shared__ float red[4];
#pragma unroll
    for (int o = 16; o; o >>= 1) val += __shfl_xor_sync(0xffffffffu, val, o);
    if ((threadIdx.x & 31) == 0) red[threadIdx.x >> 5] = val;
    __syncthreads();
    if (threadIdx.x == 0) out[g] = red[0] + red[1] + red[2] + red[3] + dec_b[0];
}

// ---------------- launch ----------------
extern "C" void kernel_launch(void* const* d_in, const int* in_sizes, int n_in,
                              void* d_out, int out_size) {
    const float* nodes     = (const float*)d_in[0];
    const int*   senders   = (const int*)d_in[1];
    const int*   receivers = (const int*)d_in[2];
    // d_in[3] = graph_ids (contiguous blocks of 1000; not needed)
    const float* embed_w   = (const float*)d_in[4];
    const float* embed_b   = (const float*)d_in[5];
    const float* mlp_w     = (const float*)d_in[6];
    const float* mlp_b     = (const float*)d_in[7];
    const float* ln_scale  = (const float*)d_in[8];
    const float* ln_offset = (const float*)d_in[9];
    const float* dec_w     = (const float*)d_in[10];
    const float* dec_b     = (const float*)d_in[11];
    float* out = (float*)d_out;

    float *ph, *pa, *pb;
    cudaGetSymbolAddress((void**)&ph, g_h);
    cudaGetSymbolAddress((void**)&pa, g_a);
    cudaGetSymbolAddress((void**)&pb, g_b);

    cudaFuncSetAttribute(k_gemm_h2<64, 0>,  cudaFuncAttributeMaxDynamicSharedMemorySize, SM_GEMM_TOTAL);
    cudaFuncSetAttribute(k_gemm_h2<128, 1>, cudaFuncAttributeMaxDynamicSharedMemorySize, SM_GEMM_TOTAL);
    cudaFuncSetAttribute(k_gemm_h2<128, 2>, cudaFuncAttributeMaxDynamicSharedMemorySize, SM_GEMM_TOTAL);

    // degrees
    k_zero_deg<<<(N_NODES + 255) / 256, 256>>>();
    k_count<<<(N_EDGES + 255) / 256, 256>>>(senders, receivers);
    k_inv<<<(N_NODES + 255) / 256, 256>>>();

    const int gemm_grid = (N_NODES + 127) / 128;   // 782

    // embed: h = nodes @ embed_w + embed_b
    k_gemm_h2<64, 0><<<gemm_grid, 512, SM_GEMM_TOTAL>>>(nodes, embed_w, embed_b, ph, nullptr, N_NODES);

    const int row_grid  = (N_NODES * 32 + 255) / 256;   // warp-per-row
    const int edge_grid = (N_EDGES * 32 + 255) / 256;   // warp-per-edge

    for (int s = 0; s < 2; s++) {
        const float* W0 = mlp_w + (size_t)(s * 2 + 0) * LATENT * LATENT;
        const float* W1 = mlp_w + (size_t)(s * 2 + 1) * LATENT * LATENT;
        const float* b0 = mlp_b + (size_t)(s * 2 + 0) * LATENT;
        const float* b1 = mlp_b + (size_t)(s * 2 + 1) * LATENT;

        // hidden = relu(h @ W0 + b0)
        k_gemm_h2<128, 1><<<gemm_grid, 512, SM_GEMM_TOTAL>>>(ph, W0, b0, pa, nullptr, N_NODES);
        // xs (pb) = relu(hidden @ W1 + b1) * inv_sqrt_sdeg; agg (pa) = xs (self-loop)
        k_gemm_h2<128, 2><<<gemm_grid, 512, SM_GEMM_TOTAL>>>(pa, W1, b1, pb, pa, N_NODES);
        // agg[r] += xs[s]
        k_edge<<<edge_grid, 256>>>(senders, receivers, pb, pa);
        // h = LN(agg * inv_sqrt_rdeg + h)
        k_ln<<<row_grid, 256>>>(pa, ph, ln_scale + s * LATENT, ln_offset + s * LATENT);
    }

    k_pool<<<N_GRAPH, 128>>>(dec_w, dec_b, out);
}

// round 5
// speedup vs baseline: 2.7017x; 1.5917x over previous
#include <cuda_runtime.h>
#include <cuda_fp16.h>
#include <cstdint>

#define N_NODES 100000
#define N_EDGES 1600000
#define N_GRAPH 100
#define IN_DIM 64
#define LATENT 128
#define LN_EPS 1e-5f

// ---------------- scratch (device globals; no allocation allowed) ----------------
__device__ float g_h[(size_t)N_NODES * LATENT];   // node state
__device__ float g_a[(size_t)N_NODES * LATENT];   // mlp hidden scratch
__device__ float g_b[(size_t)N_NODES * LATENT];   // xs (scaled mlp out)
__device__ int   g_cs[N_NODES];
__device__ int   g_cr[N_NODES];
__device__ float g_invs[N_NODES];
__device__ float g_invr[N_NODES];
__device__ int   g_start[N_NODES];   // CSR segment start (by receiver)
__device__ int   g_fill[N_NODES];    // fill cursor per node
__device__ int   g_csr[N_EDGES];     // sender index per CSR slot
__device__ int   g_cursor;

// ---------------- degree / CSR kernels ----------------
__global__ void k_zero_deg() {
    int i = blockIdx.x * blockDim.x + threadIdx.x;
    if (i < N_NODES) { g_cs[i] = 0; g_cr[i] = 0; }
    if (i == 0) g_cursor = 0;
}
__global__ void k_count(const int* __restrict__ senders, const int* __restrict__ receivers) {
    int e = blockIdx.x * blockDim.x + threadIdx.x;
    if (e < N_EDGES) {
        atomicAdd(&g_cs[senders[e]], 1);
        atomicAdd(&g_cr[receivers[e]], 1);
    }
}
__global__ void k_inv() {
    int i = blockIdx.x * blockDim.x + threadIdx.x;
    if (i < N_NODES) {
        g_invs[i] = rsqrtf((float)(g_cs[i] + 1));
        g_invr[i] = rsqrtf((float)(g_cr[i] + 1));
        int st = atomicAdd(&g_cursor, g_cr[i]);   // segment allocation (order-free)
        g_start[i] = st;
        g_fill[i] = st;
    }
}
__global__ void k_fill(const int* __restrict__ senders, const int* __restrict__ receivers) {
    int e = blockIdx.x * blockDim.x + threadIdx.x;
    if (e < N_EDGES) {
        int r = receivers[e];
        int pos = atomicAdd(&g_fill[r], 1);
        g_csr[pos] = senders[e];
    }
}

// ---------------- fp16 helpers ----------------
__device__ __forceinline__ void hilo(float x, __half& h, float& res) {
    h = __float2half_rn(x);
    res = x - __half2float(h);
}
__device__ __forceinline__ uint32_t pack2(__half a, __half b) {
    __half2 h = __halves2half2(a, b);
    return *(uint32_t*)&h;
}
__device__ __forceinline__ void mma_f16(float c[4], const uint32_t a[4],
                                        uint32_t b0, uint32_t b1) {
    asm volatile(
        "mma.sync.aligned.m16n8k16.row.col.f32.f16.f16.f32 "
        "{%0,%1,%2,%3}, {%4,%5,%6,%7}, {%8,%9}, {%0,%1,%2,%3};"
        : "+f"(c[0]), "+f"(c[1]), "+f"(c[2]), "+f"(c[3])
        : "r"(a[0]), "r"(a[1]), "r"(a[2]), "r"(a[3]),
          "r"(b0), "r"(b1));
}

// ---------------- warp-MMA fp16 GEMM, hi/lo split (~fp32 accuracy) ----------------
// MODE 0: +bias   MODE 1: +bias,relu   MODE 2: +bias,relu,*g_invs[row]
#define S2 36
#define TILEW (128 * S2)

template<int KTOT, int MODE>
__global__ __launch_bounds__(512, 2)
void k_gemm_h2(const float* __restrict__ A, const float* __restrict__ W,
               const float* __restrict__ bias, float* __restrict__ C, int M) {
    extern __shared__ uint32_t sm[];
    uint32_t* sAhi = sm;
    uint32_t* sAlo = sAhi + TILEW;
    uint32_t* sBhi = sAlo + TILEW;
    uint32_t* sBlo = sBhi + TILEW;
    float*    sBias = (float*)(sBlo + TILEW);

    const int tid  = threadIdx.x;
    const int lane = tid & 31;
    const int wid  = tid >> 5;
    const int grp  = lane >> 2;
    const int tig  = lane & 3;
    const int wm   = wid & 3;
    const int wn   = wid >> 2;
    const int row0 = blockIdx.x * 128;

    if (tid < 128) sBias[tid] = bias[tid];

    float acc[2][4][4];
#pragma unroll
    for (int i = 0; i < 2; i++)
#pragma unroll
        for (int j = 0; j < 4; j++)
#pragma unroll
            for (int q = 0; q < 4; q++) acc[i][j][q] = 0.f;

    const int n_chunks = KTOT / 64;
    for (int ch = 0; ch < n_chunks; ch++) {
        if (ch) __syncthreads();
#pragma unroll
        for (int it = 0; it < 4; it++) {
            int i  = tid + it * 512;
            int r  = i >> 4;
            int c4 = (i & 15) * 4;
            float4 v = make_float4(0.f, 0.f, 0.f, 0.f);
            if (row0 + r < M)
                v = *(const float4*)&A[(size_t)(row0 + r) * KTOT + ch * 64 + c4];
            __half h0, h1, h2, h3; float r0, r1, r2, r3;
            hilo(v.x, h0, r0); hilo(v.y, h1, r1);
            hilo(v.z, h2, r2); hilo(v.w, h3, r3);
            int w = r * S2 + (c4 >> 1);
            *(uint2*)&sAhi[w] = make_uint2(pack2(h0, h1), pack2(h2, h3));
            *(uint2*)&sAlo[w] = make_uint2(
                pack2(__float2half_rn(r0), __float2half_rn(r1)),
                pack2(__float2half_rn(r2), __float2half_rn(r3)));
        }
#pragma unroll
        for (int it = 0; it < 8; it++) {
            int i  = tid + it * 512;
            int n  = i & 127;
            int kp = i >> 7;
            const float* wp = &W[(size_t)(ch * 64 + 2 * kp) * 128 + n];
            float v0 = __ldg(wp), v1 = __ldg(wp + 128);
            __half h0, h1; float r0, r1;
            hilo(v0, h0, r0); hilo(v1, h1, r1);
            sBhi[n * S2 + kp] = pack2(h0, h1);
            sBlo[n * S2 + kp] = pack2(__float2half_rn(r0), __float2half_rn(r1));
        }
        __syncthreads();

#pragma unroll
        for (int ks = 0; ks < 4; ks++) {
            const int kb = ks * 8;
            uint32_t aH[2][4], aL[2][4];
#pragma unroll
            for (int mt = 0; mt < 2; mt++) {
                int base = (wm * 32 + mt * 16 + grp) * S2 + kb + tig;
                aH[mt][0] = sAhi[base];
                aH[mt][1] = sAhi[base + 8 * S2];
                aH[mt][2] = sAhi[base + 4];
                aH[mt][3] = sAhi[base + 8 * S2 + 4];
                aL[mt][0] = sAlo[base];
                aL[mt][1] = sAlo[base + 8 * S2];
                aL[mt][2] = sAlo[base + 4];
                aL[mt][3] = sAlo[base + 8 * S2 + 4];
            }
#pragma unroll
            for (int nt = 0; nt < 4; nt++) {
                int bb = (wn * 32 + nt * 8 + grp) * S2 + kb + tig;
                uint32_t bh0 = sBhi[bb], bh1 = sBhi[bb + 4];
                uint32_t bl0 = sBlo[bb], bl1 = sBlo[bb + 4];
#pragma unroll
                for (int mt = 0; mt < 2; mt++) {
                    mma_f16(acc[mt][nt], aH[mt], bh0, bh1);
                    mma_f16(acc[mt][nt], aH[mt], bl0, bl1);
                    mma_f16(acc[mt][nt], aL[mt], bh0, bh1);
                }
            }
        }
    }

#pragma unroll
    for (int mt = 0; mt < 2; mt++) {
        int ra = row0 + wm * 32 + mt * 16 + grp;
        int rb = ra + 8;
        float sa = 1.f, sb = 1.f;
        if (MODE == 2) {
            if (ra < M) sa = g_invs[ra];
            if (rb < M) sb = g_invs[rb];
        }
#pragma unroll
        for (int nt = 0; nt < 4; nt++) {
            int col = wn * 32 + nt * 8 + 2 * tig;
            float b0 = sBias[col], b1 = sBias[col + 1];
            float v0 = acc[mt][nt][0] + b0;
            float v1 = acc[mt][nt][1] + b1;
            float v2 = acc[mt][nt][2] + b0;
            float v3 = acc[mt][nt][3] + b1;
            if (MODE >= 1) {
                v0 = fmaxf(v0, 0.f); v1 = fmaxf(v1, 0.f);
                v2 = fmaxf(v2, 0.f); v3 = fmaxf(v3, 0.f);
            }
            if (MODE == 2) { v0 *= sa; v1 *= sa; v2 *= sb; v3 *= sb; }
            if (ra < M) *(float2*)&C[(size_t)ra * 128 + col] = make_float2(v0, v1);
            if (rb < M) *(float2*)&C[(size_t)rb * 128 + col] = make_float2(v2, v3);
        }
    }
}

#define SM_GEMM_TOTAL (4 * TILEW * 4 + 128 * 4)   // ~74 KB

// ---------------- fused CSR gather + skip + LayerNorm: one warp per node ----------------
// h[node] = LN( (xs[node] + sum_{e in in(node)} xs[csr[e]]) * invr[node] + h[node] )
__global__ __launch_bounds__(256)
void k_gln(const float* __restrict__ xs, float* __restrict__ h,
           const float* __restrict__ scale, const float* __restrict__ offset) {
    int node = (blockIdx.x * blockDim.x + threadIdx.x) >> 5;
    int lane = threadIdx.x & 31;
    if (node >= N_NODES) return;
    const int c = lane * 4;

    float4 acc = *(const float4*)&xs[(size_t)node * 128 + c];   // self-loop
    const int beg = g_start[node];
    const int end = beg + g_cr[node];

    for (int base = beg; base < end; base += 32) {
        int idx = (base + lane < end) ? g_csr[base + lane] : 0;
        int m = min(32, end - base);
        int j = 0;
        for (; j + 4 <= m; j += 4) {
            int s0 = __shfl_sync(0xffffffffu, idx, j);
            int s1 = __shfl_sync(0xffffffffu, idx, j + 1);
            int s2 = __shfl_sync(0xffffffffu, idx, j + 2);
            int s3 = __shfl_sync(0xffffffffu, idx, j + 3);
            float4 v0 = *(const float4*)&xs[(size_t)s0 * 128 + c];
            float4 v1 = *(const float4*)&xs[(size_t)s1 * 128 + c];
            float4 v2 = *(const float4*)&xs[(size_t)s2 * 128 + c];
            float4 v3 = *(const float4*)&xs[(size_t)s3 * 128 + c];
            acc.x += v0.x + v1.x + v2.x + v3.x;
            acc.y += v0.y + v1.y + v2.y + v3.y;
            acc.z += v0.z + v1.z + v2.z + v3.z;
            acc.w += v0.w + v1.w + v2.w + v3.w;
        }
        for (; j < m; j++) {
            int s = __shfl_sync(0xffffffffu, idx, j);
            float4 v = *(const float4*)&xs[(size_t)s * 128 + c];
            acc.x += v.x; acc.y += v.y; acc.z += v.z; acc.w += v.w;
        }
    }

    float ir = g_invr[node];
    float4 vh = *(const float4*)&h[(size_t)node * 128 + c];
    float4 y;
    y.x = acc.x * ir + vh.x; y.y = acc.y * ir + vh.y;
    y.z = acc.z * ir + vh.z; y.w = acc.w * ir + vh.w;

    float sum = y.x + y.y + y.z + y.w;
    float sq  = y.x * y.x + y.y * y.y + y.z * y.z + y.w * y.w;
#pragma unroll
    for (int o = 16; o; o >>= 1) {
        sum += __shfl_xor_sync(0xffffffffu, sum, o);
        sq  += __shfl_xor_sync(0xffffffffu, sq, o);
    }
    float mean = sum * (1.f / 128.f);
    float var  = sq * (1.f / 128.f) - mean * mean;
    float rs = rsqrtf(var + LN_EPS);
    float4 scv = *(const float4*)&scale[c];
    float4 ofv = *(const float4*)&offset[c];
    y.x = (y.x - mean) * rs * scv.x + ofv.x;
    y.y = (y.y - mean) * rs * scv.y + ofv.y;
    y.z = (y.z - mean) * rs * scv.z + ofv.z;
    y.w = (y.w - mean) * rs * scv.w + ofv.w;
    *(float4*)&h[(size_t)node * 128 + c] = y;
}

// ---------------- pool (segment mean, contiguous 1000-node graphs) + decode ----------------
__global__ __launch_bounds__(128)
void k_pool(const float* __restrict__ dec_w, const float* __restrict__ dec_b,
            float* __restrict__ out) {
    int g = blockIdx.x;
    int c = threadIdx.x;
    const int per = N_NODES / N_GRAPH;
    const float* base = g_h + (size_t)g * per * 128;
    float sum = 0.f;
#pragma unroll 8
    for (int r = 0; r < per; r++) sum += base[(size_t)r * 128 + c];
    float val = (sum * (1.f / (float)per)) * dec_w[c];
    __shared__ float red[4];
#pragma unroll
    for (int o = 16; o; o >>= 1) val += __shfl_xor_sync(0xffffffffu, val, o);
    if ((threadIdx.x & 31) == 0) red[threadIdx.x >> 5] = val;
    __syncthreads();
    if (threadIdx.x == 0) out[g] = red[0] + red[1] + red[2] + red[3] + dec_b[0];
}

// ---------------- launch ----------------
extern "C" void kernel_launch(void* const* d_in, const int* in_sizes, int n_in,
                              void* d_out, int out_size) {
    const float* nodes     = (const float*)d_in[0];
    const int*   senders   = (const int*)d_in[1];
    const int*   receivers = (const int*)d_in[2];
    const float* embed_w   = (const float*)d_in[4];
    const float* embed_b   = (const float*)d_in[5];
    const float* mlp_w     = (const float*)d_in[6];
    const float* mlp_b     = (const float*)d_in[7];
    const float* ln_scale  = (const float*)d_in[8];
    const float* ln_offset = (const float*)d_in[9];
    const float* dec_w     = (const float*)d_in[10];
    const float* dec_b     = (const float*)d_in[11];
    float* out = (float*)d_out;

    float *ph, *pa, *pb;
    cudaGetSymbolAddress((void**)&ph, g_h);
    cudaGetSymbolAddress((void**)&pa, g_a);
    cudaGetSymbolAddress((void**)&pb, g_b);

    cudaFuncSetAttribute(k_gemm_h2<64, 0>,  cudaFuncAttributeMaxDynamicSharedMemorySize, SM_GEMM_TOTAL);
    cudaFuncSetAttribute(k_gemm_h2<128, 1>, cudaFuncAttributeMaxDynamicSharedMemorySize, SM_GEMM_TOTAL);
    cudaFuncSetAttribute(k_gemm_h2<128, 2>, cudaFuncAttributeMaxDynamicSharedMemorySize, SM_GEMM_TOTAL);

    // degrees + CSR build
    k_zero_deg<<<(N_NODES + 255) / 256, 256>>>();
    k_count<<<(N_EDGES + 255) / 256, 256>>>(senders, receivers);
    k_inv<<<(N_NODES + 255) / 256, 256>>>();
    k_fill<<<(N_EDGES + 255) / 256, 256>>>(senders, receivers);

    const int gemm_grid = (N_NODES + 127) / 128;

    // embed: h = nodes @ embed_w + embed_b
    k_gemm_h2<64, 0><<<gemm_grid, 512, SM_GEMM_TOTAL>>>(nodes, embed_w, embed_b, ph, N_NODES);

    const int row_grid = (N_NODES * 32 + 255) / 256;

    for (int s = 0; s < 2; s++) {
        const float* W0 = mlp_w + (size_t)(s * 2 + 0) * LATENT * LATENT;
        const float* W1 = mlp_w + (size_t)(s * 2 + 1) * LATENT * LATENT;
        const float* b0 = mlp_b + (size_t)(s * 2 + 0) * LATENT;
        const float* b1 = mlp_b + (size_t)(s * 2 + 1) * LATENT;

        // hidden = relu(h @ W0 + b0)
        k_gemm_h2<128, 1><<<gemm_grid, 512, SM_GEMM_TOTAL>>>(ph, W0, b0, pa, N_NODES);
        // xs = relu(hidden @ W1 + b1) * inv_sqrt_sdeg
        k_gemm_h2<128, 2><<<gemm_grid, 512, SM_GEMM_TOTAL>>>(pa, W1, b1, pb, N_NODES);
        // h = LN((xs[self] + sum_in xs) * inv_sqrt_rdeg + h)
        k_gln<<<row_grid, 256>>>(pb, ph, ln_scale + s * LATENT, ln_offset + s * LATENT);
    }

    k_pool<<<N_GRAPH, 128>>>(dec_w, dec_b, out);
}

// round 6
// speedup vs baseline: 2.8209x; 1.0441x over previous
#include <cuda_runtime.h>
#include <cuda_fp16.h>
#include <cstdint>

#define N_NODES 100000
#define N_EDGES 1600000
#define N_GRAPH 100
#define IN_DIM 64
#define LATENT 128
#define LN_EPS 1e-5f

// ---------------- scratch (device globals; no allocation allowed) ----------------
__device__ float g_h[(size_t)N_NODES * LATENT];   // node state
__device__ float g_a[(size_t)N_NODES * LATENT];   // mlp hidden scratch
__device__ float g_b[(size_t)N_NODES * LATENT];   // xs (scaled mlp out)
__device__ int   g_cs[N_NODES];
__device__ int   g_cr[N_NODES];
__device__ float g_invs[N_NODES];
__device__ float g_invr[N_NODES];
__device__ int   g_start[N_NODES];   // CSR segment start (by receiver)
__device__ int   g_fill[N_NODES];    // fill cursor per node
__device__ int   g_csr[N_EDGES];     // sender index per CSR slot
__device__ int   g_cursor;
// pre-converted weights: packed half2 hi/lo words, layout [n][kp]
// embed (K=64): 128*32 = 4096 words at offset 0; mlp g (K=128): 128*64 = 8192 at 4096+g*8192
#define WCONV_WORDS (4096 + 4 * 8192)
__device__ uint32_t g_whi[WCONV_WORDS];
__device__ uint32_t g_wlo[WCONV_WORDS];

// ---------------- degree / CSR kernels ----------------
__global__ void k_zero_deg() {
    int i = blockIdx.x * blockDim.x + threadIdx.x;
    if (i < N_NODES) { g_cs[i] = 0; g_cr[i] = 0; }
    if (i == 0) g_cursor = 0;
}
__global__ void k_count(const int* __restrict__ senders, const int* __restrict__ receivers) {
    int e = blockIdx.x * blockDim.x + threadIdx.x;
    if (e < N_EDGES) {
        atomicAdd(&g_cs[senders[e]], 1);
        atomicAdd(&g_cr[receivers[e]], 1);
    }
}
__global__ void k_inv() {
    int i = blockIdx.x * blockDim.x + threadIdx.x;
    if (i < N_NODES) {
        g_invs[i] = rsqrtf((float)(g_cs[i] + 1));
        g_invr[i] = rsqrtf((float)(g_cr[i] + 1));
        int st = atomicAdd(&g_cursor, g_cr[i]);   // segment allocation (order-free)
        g_start[i] = st;
        g_fill[i] = st;
    }
}
__global__ void k_fill(const int* __restrict__ senders, const int* __restrict__ receivers) {
    int e = blockIdx.x * blockDim.x + threadIdx.x;
    if (e < N_EDGES) {
        int r = receivers[e];
        int pos = atomicAdd(&g_fill[r], 1);
        g_csr[pos] = senders[e];
    }
}

// ---------------- fp16 helpers ----------------
__device__ __forceinline__ void hilo(float x, __half& h, float& res) {
    h = __float2half_rn(x);
    res = x - __half2float(h);
}
__device__ __forceinline__ uint32_t pack2(__half a, __half b) {
    __half2 h = __halves2half2(a, b);
    return *(uint32_t*)&h;
}
__device__ __forceinline__ void mma_f16(float c[4], const uint32_t a[4],
                                        uint32_t b0, uint32_t b1) {
    asm volatile(
        "mma.sync.aligned.m16n8k16.row.col.f32.f16.f16.f32 "
        "{%0,%1,%2,%3}, {%4,%5,%6,%7}, {%8,%9}, {%0,%1,%2,%3};"
        : "+f"(c[0]), "+f"(c[1]), "+f"(c[2]), "+f"(c[3])
        : "r"(a[0]), "r"(a[1]), "r"(a[2]), "r"(a[3]),
          "r"(b0), "r"(b1));
}

// ---------------- weight pre-conversion (one tiny kernel) ----------------
__global__ void k_wconv(const float* __restrict__ embed_w, const float* __restrict__ mlp_w) {
    int i = blockIdx.x * blockDim.x + threadIdx.x;
    if (i >= WCONV_WORDS) return;
    float v0, v1;
    if (i < 4096) {                       // embed: K=64, words/row = 32
        int n = i >> 5, kp = i & 31;
        v0 = embed_w[(size_t)(2 * kp) * 128 + n];
        v1 = embed_w[(size_t)(2 * kp + 1) * 128 + n];
    } else {                              // mlp g: K=128, words/row = 64
        int j = i - 4096;
        int g = j >> 13;
        int r = j & 8191;
        int n = r >> 6, kp = r & 63;
        const float* W = mlp_w + (size_t)g * 128 * 128;
        v0 = W[(size_t)(2 * kp) * 128 + n];
        v1 = W[(size_t)(2 * kp + 1) * 128 + n];
    }
    __half h0, h1; float r0, r1;
    hilo(v0, h0, r0); hilo(v1, h1, r1);
    g_whi[i] = pack2(h0, h1);
    g_wlo[i] = pack2(__float2half_rn(r0), __float2half_rn(r1));
}

// ---------------- warp-MMA fp16 GEMM, hi/lo split (~fp32 accuracy) ----------------
// MODE 0: +bias   MODE 1: +bias,relu   MODE 2: +bias,relu,*g_invs[row]
// B operand comes pre-converted from g_whi/g_wlo (layout [n][KTOT/2] words).
#define S2 36
#define TILEW (128 * S2)

template<int KTOT, int MODE>
__global__ __launch_bounds__(512, 2)
void k_gemm_h2(const float* __restrict__ A,
               const uint32_t* __restrict__ Whi, const uint32_t* __restrict__ Wlo,
               const float* __restrict__ bias, float* __restrict__ C, int M) {
    extern __shared__ uint32_t sm[];
    uint32_t* sAhi = sm;
    uint32_t* sAlo = sAhi + TILEW;
    uint32_t* sBhi = sAlo + TILEW;
    uint32_t* sBlo = sBhi + TILEW;
    float*    sBias = (float*)(sBlo + TILEW);

    const int tid  = threadIdx.x;
    const int lane = tid & 31;
    const int wid  = tid >> 5;
    const int grp  = lane >> 2;
    const int tig  = lane & 3;
    const int wm   = wid & 3;
    const int wn   = wid >> 2;
    const int row0 = blockIdx.x * 128;
    const int WPR  = KTOT / 2;            // global words per row of W

    if (tid < 128) sBias[tid] = bias[tid];

    float acc[2][4][4];
#pragma unroll
    for (int i = 0; i < 2; i++)
#pragma unroll
        for (int j = 0; j < 4; j++)
#pragma unroll
            for (int q = 0; q < 4; q++) acc[i][j][q] = 0.f;

    const int n_chunks = KTOT / 64;
    for (int ch = 0; ch < n_chunks; ch++) {
        if (ch) __syncthreads();
        // ---- stage A chunk [128 rows x 64 k] as fp16 hi/lo ----
#pragma unroll
        for (int it = 0; it < 4; it++) {
            int i  = tid + it * 512;
            int r  = i >> 4;
            int c4 = (i & 15) * 4;
            float4 v = make_float4(0.f, 0.f, 0.f, 0.f);
            if (row0 + r < M)
                v = *(const float4*)&A[(size_t)(row0 + r) * KTOT + ch * 64 + c4];
            __half h0, h1, h2, h3; float r0, r1, r2, r3;
            hilo(v.x, h0, r0); hilo(v.y, h1, r1);
            hilo(v.z, h2, r2); hilo(v.w, h3, r3);
            int w = r * S2 + (c4 >> 1);
            *(uint2*)&sAhi[w] = make_uint2(pack2(h0, h1), pack2(h2, h3));
            *(uint2*)&sAlo[w] = make_uint2(
                pack2(__float2half_rn(r0), __float2half_rn(r1)),
                pack2(__float2half_rn(r2), __float2half_rn(r3)));
        }
        // ---- stage B chunk: plain copy of pre-converted words (8 uint4 per row) ----
#pragma unroll
        for (int it = 0; it < 2; it++) {
            int i = tid + it * 512;           // 1024 uint4 total
            int n = i >> 3;
            int q = (i & 7) * 4;              // kp within chunk
            int gw = n * WPR + ch * 32 + q;
            int sw = n * S2 + q;
            *(uint4*)&sBhi[sw] = *(const uint4*)&Whi[gw];
            *(uint4*)&sBlo[sw] = *(const uint4*)&Wlo[gw];
        }
        __syncthreads();

#pragma unroll
        for (int ks = 0; ks < 4; ks++) {
            const int kb = ks * 8;
            uint32_t aH[2][4], aL[2][4];
#pragma unroll
            for (int mt = 0; mt < 2; mt++) {
                int base = (wm * 32 + mt * 16 + grp) * S2 + kb + tig;
                aH[mt][0] = sAhi[base];
                aH[mt][1] = sAhi[base + 8 * S2];
                aH[mt][2] = sAhi[base + 4];
                aH[mt][3] = sAhi[base + 8 * S2 + 4];
                aL[mt][0] = sAlo[base];
                aL[mt][1] = sAlo[base + 8 * S2];
                aL[mt][2] = sAlo[base + 4];
                aL[mt][3] = sAlo[base + 8 * S2 + 4];
            }
#pragma unroll
            for (int nt = 0; nt < 4; nt++) {
                int bb = (wn * 32 + nt * 8 + grp) * S2 + kb + tig;
                uint32_t bh0 = sBhi[bb], bh1 = sBhi[bb + 4];
                uint32_t bl0 = sBlo[bb], bl1 = sBlo[bb + 4];
#pragma unroll
                for (int mt = 0; mt < 2; mt++) {
                    mma_f16(acc[mt][nt], aH[mt], bh0, bh1);
                    mma_f16(acc[mt][nt], aH[mt], bl0, bl1);
                    mma_f16(acc[mt][nt], aL[mt], bh0, bh1);
                }
            }
        }
    }

#pragma unroll
    for (int mt = 0; mt < 2; mt++) {
        int ra = row0 + wm * 32 + mt * 16 + grp;
        int rb = ra + 8;
        float sa = 1.f, sb = 1.f;
        if (MODE == 2) {
            if (ra < M) sa = g_invs[ra];
            if (rb < M) sb = g_invs[rb];
        }
#pragma unroll
        for (int nt = 0; nt < 4; nt++) {
            int col = wn * 32 + nt * 8 + 2 * tig;
            float b0 = sBias[col], b1 = sBias[col + 1];
            float v0 = acc[mt][nt][0] + b0;
            float v1 = acc[mt][nt][1] + b1;
            float v2 = acc[mt][nt][2] + b0;
            float v3 = acc[mt][nt][3] + b1;
            if (MODE >= 1) {
                v0 = fmaxf(v0, 0.f); v1 = fmaxf(v1, 0.f);
                v2 = fmaxf(v2, 0.f); v3 = fmaxf(v3, 0.f);
            }
            if (MODE == 2) { v0 *= sa; v1 *= sa; v2 *= sb; v3 *= sb; }
            if (ra < M) *(float2*)&C[(size_t)ra * 128 + col] = make_float2(v0, v1);
            if (rb < M) *(float2*)&C[(size_t)rb * 128 + col] = make_float2(v2, v3);
        }
    }
}

#define SM_GEMM_TOTAL (4 * TILEW * 4 + 128 * 4)   // ~74 KB

// ---------------- fused CSR gather + skip + LayerNorm: one warp per node ----------------
__global__ __launch_bounds__(256)
void k_gln(const float* __restrict__ xs, float* __restrict__ h,
           const float* __restrict__ scale, const float* __restrict__ offset) {
    int node = (blockIdx.x * blockDim.x + threadIdx.x) >> 5;
    int lane = threadIdx.x & 31;
    if (node >= N_NODES) return;
    const int c = lane * 4;

    float4 acc = *(const float4*)&xs[(size_t)node * 128 + c];   // self-loop
    const int beg = g_start[node];
    const int end = beg + g_cr[node];

    for (int base = beg; base < end; base += 32) {
        int idx = (base + lane < end) ? g_csr[base + lane] : 0;
        int m = min(32, end - base);
        int j = 0;
        for (; j + 4 <= m; j += 4) {
            int s0 = __shfl_sync(0xffffffffu, idx, j);
            int s1 = __shfl_sync(0xffffffffu, idx, j + 1);
            int s2 = __shfl_sync(0xffffffffu, idx, j + 2);
            int s3 = __shfl_sync(0xffffffffu, idx, j + 3);
            float4 v0 = *(const float4*)&xs[(size_t)s0 * 128 + c];
            float4 v1 = *(const float4*)&xs[(size_t)s1 * 128 + c];
            float4 v2 = *(const float4*)&xs[(size_t)s2 * 128 + c];
            float4 v3 = *(const float4*)&xs[(size_t)s3 * 128 + c];
            acc.x += v0.x + v1.x + v2.x + v3.x;
            acc.y += v0.y + v1.y + v2.y + v3.y;
            acc.z += v0.z + v1.z + v2.z + v3.z;
            acc.w += v0.w + v1.w + v2.w + v3.w;
        }
        for (; j < m; j++) {
            int s = __shfl_sync(0xffffffffu, idx, j);
            float4 v = *(const float4*)&xs[(size_t)s * 128 + c];
            acc.x += v.x; acc.y += v.y; acc.z += v.z; acc.w += v.w;
        }
    }

    float ir = g_invr[node];
    float4 vh = *(const float4*)&h[(size_t)node * 128 + c];
    float4 y;
    y.x = acc.x * ir + vh.x; y.y = acc.y * ir + vh.y;
    y.z = acc.z * ir + vh.z; y.w = acc.w * ir + vh.w;

    float sum = y.x + y.y + y.z + y.w;
    float sq  = y.x * y.x + y.y * y.y + y.z * y.z + y.w * y.w;
#pragma unroll
    for (int o = 16; o; o >>= 1) {
        sum += __shfl_xor_sync(0xffffffffu, sum, o);
        sq  += __shfl_xor_sync(0xffffffffu, sq, o);
    }
    float mean = sum * (1.f / 128.f);
    float var  = sq * (1.f / 128.f) - mean * mean;
    float rs = rsqrtf(var + LN_EPS);
    float4 scv = *(const float4*)&scale[c];
    float4 ofv = *(const float4*)&offset[c];
    y.x = (y.x - mean) * rs * scv.x + ofv.x;
    y.y = (y.y - mean) * rs * scv.y + ofv.y;
    y.z = (y.z - mean) * rs * scv.z + ofv.z;
    y.w = (y.w - mean) * rs * scv.w + ofv.w;
    *(float4*)&h[(size_t)node * 128 + c] = y;
}

// ---------------- pool (segment mean, contiguous 1000-node graphs) + decode ----------------
__global__ __launch_bounds__(128)
void k_pool(const float* __restrict__ dec_w, const float* __restrict__ dec_b,
            float* __restrict__ out) {
    int g = blockIdx.x;
    int c = threadIdx.x;
    const int per = N_NODES / N_GRAPH;
    const float* base = g_h + (size_t)g * per * 128;
    float sum = 0.f;
#pragma unroll 8
    for (int r = 0; r < per; r++) sum += base[(size_t)r * 128 + c];
    float val = (sum * (1.f / (float)per)) * dec_w[c];
    __shared__ float red[4];
#pragma unroll
    for (int o = 16; o; o >>= 1) val += __shfl_xor_sync(0xffffffffu, val, o);
    if ((threadIdx.x & 31) == 0) red[threadIdx.x >> 5] = val;
    __syncthreads();
    if (threadIdx.x == 0) out[g] = red[0] + red[1] + red[2] + red[3] + dec_b[0];
}

// ---------------- launch ----------------
extern "C" void kernel_launch(void* const* d_in, const int* in_sizes, int n_in,
                              void* d_out, int out_size) {
    const float* nodes     = (const float*)d_in[0];
    const int*   senders   = (const int*)d_in[1];
    const int*   receivers = (const int*)d_in[2];
    const float* embed_w   = (const float*)d_in[4];
    const float* embed_b   = (const float*)d_in[5];
    const float* mlp_w     = (const float*)d_in[6];
    const float* mlp_b     = (const float*)d_in[7];
    const float* ln_scale  = (const float*)d_in[8];
    const float* ln_offset = (const float*)d_in[9];
    const float* dec_w     = (const float*)d_in[10];
    const float* dec_b     = (const float*)d_in[11];
    float* out = (float*)d_out;

    float *ph, *pa, *pb;
    uint32_t *pwhi, *pwlo;
    cudaGetSymbolAddress((void**)&ph, g_h);
    cudaGetSymbolAddress((void**)&pa, g_a);
    cudaGetSymbolAddress((void**)&pb, g_b);
    cudaGetSymbolAddress((void**)&pwhi, g_whi);
    cudaGetSymbolAddress((void**)&pwlo, g_wlo);

    cudaFuncSetAttribute(k_gemm_h2<64, 0>,  cudaFuncAttributeMaxDynamicSharedMemorySize, SM_GEMM_TOTAL);
    cudaFuncSetAttribute(k_gemm_h2<128, 1>, cudaFuncAttributeMaxDynamicSharedMemorySize, SM_GEMM_TOTAL);
    cudaFuncSetAttribute(k_gemm_h2<128, 2>, cudaFuncAttributeMaxDynamicSharedMemorySize, SM_GEMM_TOTAL);

    // host-side resources, created once (identical captured work every call)
    static cudaStream_t s2 = nullptr;
    static cudaEvent_t evFork = nullptr, evJoin = nullptr;
    if (!s2) {
        cudaStreamCreateWithFlags(&s2, cudaStreamNonBlocking);
        cudaEventCreateWithFlags(&evFork, cudaEventDisableTiming);
        cudaEventCreateWithFlags(&evJoin, cudaEventDisableTiming);
    }

    // ---- fork: CSR build on s2, GEMM front on main stream ----
    cudaEventRecord(evFork, 0);
    cudaStreamWaitEvent(s2, evFork, 0);
    k_zero_deg<<<(N_NODES + 255) / 256, 256, 0, s2>>>();
    k_count<<<(N_EDGES + 255) / 256, 256, 0, s2>>>(senders, receivers);
    k_inv<<<(N_NODES + 255) / 256, 256, 0, s2>>>();
    k_fill<<<(N_EDGES + 255) / 256, 256, 0, s2>>>(senders, receivers);
    cudaEventRecord(evJoin, s2);

    const int gemm_grid = (N_NODES + 127) / 128;

    // main stream: weight conversion + embed + first MLP GEMM (independent of CSR)
    k_wconv<<<(WCONV_WORDS + 255) / 256, 256>>>(embed_w, mlp_w);
    k_gemm_h2<64, 0><<<gemm_grid, 512, SM_GEMM_TOTAL>>>(nodes, pwhi, pwlo, embed_b, ph, N_NODES);

    const uint32_t* whi_mlp[4];
    const uint32_t* wlo_mlp[4];
    for (int g = 0; g < 4; g++) {
        whi_mlp[g] = pwhi + 4096 + g * 8192;
        wlo_mlp[g] = pwlo + 4096 + g * 8192;
    }

    const int row_grid = (N_NODES * 32 + 255) / 256;
    bool joined = false;

    for (int s = 0; s < 2; s++) {
        const float* b0 = mlp_b + (size_t)(s * 2 + 0) * LATENT;
        const float* b1 = mlp_b + (size_t)(s * 2 + 1) * LATENT;

        // hidden = relu(h @ W0 + b0)
        k_gemm_h2<128, 1><<<gemm_grid, 512, SM_GEMM_TOTAL>>>(ph, whi_mlp[s * 2], wlo_mlp[s * 2], b0, pa, N_NODES);
        if (!joined) {                  // g_invs / CSR needed from here on
            cudaStreamWaitEvent(0, evJoin, 0);
            joined = true;
        }
        // xs = relu(hidden @ W1 + b1) * inv_sqrt_sdeg
        k_gemm_h2<128, 2><<<gemm_grid, 512, SM_GEMM_TOTAL>>>(pa, whi_mlp[s * 2 + 1], wlo_mlp[s * 2 + 1], b1, pb, N_NODES);
        // h = LN((xs[self] + sum_in xs) * inv_sqrt_rdeg + h)
        k_gln<<<row_grid, 256>>>(pb, ph, ln_scale + s * LATENT, ln_offset + s * LATENT);
    }

    k_pool<<<N_GRAPH, 128>>>(dec_w, dec_b, out);
}

// round 7
// speedup vs baseline: 3.0941x; 1.0968x over previous
#include <cuda_runtime.h>
#include <cuda_fp16.h>
#include <cstdint>

#define N_NODES 100000
#define N_EDGES 1600000
#define N_GRAPH 100
#define IN_DIM 64
#define LATENT 128
#define LN_EPS 1e-5f

// ---------------- scratch (device globals; no allocation allowed) ----------------
__device__ float    g_h[(size_t)N_NODES * LATENT];   // node state
__device__ float    g_a[(size_t)N_NODES * LATENT];   // mlp hidden scratch
__device__ uint32_t g_x16[(size_t)N_NODES * 64];     // xs as packed half2 (64 words/row)
__device__ int   g_cs[N_NODES];
__device__ int   g_cr[N_NODES];
__device__ float g_invs[N_NODES];
__device__ float g_invr[N_NODES];
__device__ int   g_start[N_NODES];   // CSR segment start (by receiver)
__device__ int   g_fill[N_NODES];    // fill cursor per node
__device__ int   g_csr[N_EDGES];     // sender index per CSR slot
__device__ int   g_cursor;
// pre-converted weights: packed half2 hi/lo words, layout [n][kp]
#define WCONV_WORDS (4096 + 4 * 8192)
__device__ uint32_t g_whi[WCONV_WORDS];
__device__ uint32_t g_wlo[WCONV_WORDS];

// ---------------- degree / CSR kernels ----------------
__global__ void k_zero_deg() {
    int i = blockIdx.x * blockDim.x + threadIdx.x;
    if (i < N_NODES) { g_cs[i] = 0; g_cr[i] = 0; }
    if (i == 0) g_cursor = 0;
}
__global__ void k_count(const int* __restrict__ senders, const int* __restrict__ receivers) {
    int e = blockIdx.x * blockDim.x + threadIdx.x;
    if (e < N_EDGES) {
        atomicAdd(&g_cs[senders[e]], 1);
        atomicAdd(&g_cr[receivers[e]], 1);
    }
}
__global__ void k_inv() {
    int i = blockIdx.x * blockDim.x + threadIdx.x;
    if (i < N_NODES) {
        g_invs[i] = rsqrtf((float)(g_cs[i] + 1));
        g_invr[i] = rsqrtf((float)(g_cr[i] + 1));
        int st = atomicAdd(&g_cursor, g_cr[i]);
        g_start[i] = st;
        g_fill[i] = st;
    }
}
__global__ void k_fill(const int* __restrict__ senders, const int* __restrict__ receivers) {
    int e = blockIdx.x * blockDim.x + threadIdx.x;
    if (e < N_EDGES) {
        int r = receivers[e];
        int pos = atomicAdd(&g_fill[r], 1);
        g_csr[pos] = senders[e];
    }
}

// ---------------- fp16 helpers ----------------
__device__ __forceinline__ void hilo(float x, __half& h, float& res) {
    h = __float2half_rn(x);
    res = x - __half2float(h);
}
__device__ __forceinline__ uint32_t pack2(__half a, __half b) {
    __half2 h = __halves2half2(a, b);
    return *(uint32_t*)&h;
}
__device__ __forceinline__ void mma_f16(float c[4], const uint32_t a[4],
                                        uint32_t b0, uint32_t b1) {
    asm volatile(
        "mma.sync.aligned.m16n8k16.row.col.f32.f16.f16.f32 "
        "{%0,%1,%2,%3}, {%4,%5,%6,%7}, {%8,%9}, {%0,%1,%2,%3};"
        : "+f"(c[0]), "+f"(c[1]), "+f"(c[2]), "+f"(c[3])
        : "r"(a[0]), "r"(a[1]), "r"(a[2]), "r"(a[3]),
          "r"(b0), "r"(b1));
}

// ---------------- weight pre-conversion ----------------
__global__ void k_wconv(const float* __restrict__ embed_w, const float* __restrict__ mlp_w) {
    int i = blockIdx.x * blockDim.x + threadIdx.x;
    if (i >= WCONV_WORDS) return;
    float v0, v1;
    if (i < 4096) {                       // embed: K=64, 32 words/row
        int n = i >> 5, kp = i & 31;
        v0 = embed_w[(size_t)(2 * kp) * 128 + n];
        v1 = embed_w[(size_t)(2 * kp + 1) * 128 + n];
    } else {                              // mlp g: K=128, 64 words/row
        int j = i - 4096;
        int g = j >> 13;
        int r = j & 8191;
        int n = r >> 6, kp = r & 63;
        const float* W = mlp_w + (size_t)g * 128 * 128;
        v0 = W[(size_t)(2 * kp) * 128 + n];
        v1 = W[(size_t)(2 * kp + 1) * 128 + n];
    }
    __half h0, h1; float r0, r1;
    hilo(v0, h0, r0); hilo(v1, h1, r1);
    g_whi[i] = pack2(h0, h1);
    g_wlo[i] = pack2(__float2half_rn(r0), __float2half_rn(r1));
}

// ---------------- warp-MMA fp16 GEMM, hi/lo split (~fp32 accuracy) ----------------
// MODE 0: +bias -> fp32 C    MODE 1: +bias,relu -> fp32 C
// MODE 2: +bias,relu,*g_invs[row] -> packed half2 C16
#define S2 36
#define TILEW (128 * S2)

template<int KTOT, int MODE>
__global__ __launch_bounds__(512, 2)
void k_gemm_h2(const float* __restrict__ A,
               const uint32_t* __restrict__ Whi, const uint32_t* __restrict__ Wlo,
               const float* __restrict__ bias, float* __restrict__ C,
               uint32_t* __restrict__ C16, int M) {
    extern __shared__ uint32_t sm[];
    uint32_t* sAhi = sm;
    uint32_t* sAlo = sAhi + TILEW;
    uint32_t* sBhi = sAlo + TILEW;
    uint32_t* sBlo = sBhi + TILEW;
    float*    sBias = (float*)(sBlo + TILEW);

    const int tid  = threadIdx.x;
    const int lane = tid & 31;
    const int wid  = tid >> 5;
    const int grp  = lane >> 2;
    const int tig  = lane & 3;
    const int wm   = wid & 3;
    const int wn   = wid >> 2;
    const int row0 = blockIdx.x * 128;
    const int WPR  = KTOT / 2;

    if (tid < 128) sBias[tid] = bias[tid];

    float acc[2][4][4];
#pragma unroll
    for (int i = 0; i < 2; i++)
#pragma unroll
        for (int j = 0; j < 4; j++)
#pragma unroll
            for (int q = 0; q < 4; q++) acc[i][j][q] = 0.f;

    const int n_chunks = KTOT / 64;
    for (int ch = 0; ch < n_chunks; ch++) {
        if (ch) __syncthreads();
        // ---- stage A chunk [128 x 64] as fp16 hi/lo ----
#pragma unroll
        for (int it = 0; it < 4; it++) {
            int i  = tid + it * 512;
            int r  = i >> 4;
            int c4 = (i & 15) * 4;
            float4 v = make_float4(0.f, 0.f, 0.f, 0.f);
            if (row0 + r < M)
                v = *(const float4*)&A[(size_t)(row0 + r) * KTOT + ch * 64 + c4];
            __half h0, h1, h2, h3; float r0, r1, r2, r3;
            hilo(v.x, h0, r0); hilo(v.y, h1, r1);
            hilo(v.z, h2, r2); hilo(v.w, h3, r3);
            int w = r * S2 + (c4 >> 1);
            *(uint2*)&sAhi[w] = make_uint2(pack2(h0, h1), pack2(h2, h3));
            *(uint2*)&sAlo[w] = make_uint2(
                pack2(__float2half_rn(r0), __float2half_rn(r1)),
                pack2(__float2half_rn(r2), __float2half_rn(r3)));
        }
        // ---- stage B chunk: copy pre-converted words ----
#pragma unroll
        for (int it = 0; it < 2; it++) {
            int i = tid + it * 512;
            int n = i >> 3;
            int q = (i & 7) * 4;
            int gw = n * WPR + ch * 32 + q;
            int sw = n * S2 + q;
            *(uint4*)&sBhi[sw] = *(const uint4*)&Whi[gw];
            *(uint4*)&sBlo[sw] = *(const uint4*)&Wlo[gw];
        }
        __syncthreads();

#pragma unroll
        for (int ks = 0; ks < 4; ks++) {
            const int kb = ks * 8;
            uint32_t aH[2][4], aL[2][4];
#pragma unroll
            for (int mt = 0; mt < 2; mt++) {
                int base = (wm * 32 + mt * 16 + grp) * S2 + kb + tig;
                aH[mt][0] = sAhi[base];
                aH[mt][1] = sAhi[base + 8 * S2];
                aH[mt][2] = sAhi[base + 4];
                aH[mt][3] = sAhi[base + 8 * S2 + 4];
                aL[mt][0] = sAlo[base];
                aL[mt][1] = sAlo[base + 8 * S2];
                aL[mt][2] = sAlo[base + 4];
                aL[mt][3] = sAlo[base + 8 * S2 + 4];
            }
#pragma unroll
            for (int nt = 0; nt < 4; nt++) {
                int bb = (wn * 32 + nt * 8 + grp) * S2 + kb + tig;
                uint32_t bh0 = sBhi[bb], bh1 = sBhi[bb + 4];
                uint32_t bl0 = sBlo[bb], bl1 = sBlo[bb + 4];
#pragma unroll
                for (int mt = 0; mt < 2; mt++) {
                    mma_f16(acc[mt][nt], aH[mt], bh0, bh1);
                    mma_f16(acc[mt][nt], aH[mt], bl0, bl1);
                    mma_f16(acc[mt][nt], aL[mt], bh0, bh1);
                }
            }
        }
    }

#pragma unroll
    for (int mt = 0; mt < 2; mt++) {
        int ra = row0 + wm * 32 + mt * 16 + grp;
        int rb = ra + 8;
        float sa = 1.f, sb = 1.f;
        if (MODE == 2) {
            if (ra < M) sa = g_invs[ra];
            if (rb < M) sb = g_invs[rb];
        }
#pragma unroll
        for (int nt = 0; nt < 4; nt++) {
            int col = wn * 32 + nt * 8 + 2 * tig;
            float b0 = sBias[col], b1 = sBias[col + 1];
            float v0 = acc[mt][nt][0] + b0;
            float v1 = acc[mt][nt][1] + b1;
            float v2 = acc[mt][nt][2] + b0;
            float v3 = acc[mt][nt][3] + b1;
            if (MODE >= 1) {
                v0 = fmaxf(v0, 0.f); v1 = fmaxf(v1, 0.f);
                v2 = fmaxf(v2, 0.f); v3 = fmaxf(v3, 0.f);
            }
            if (MODE == 2) {
                v0 *= sa; v1 *= sa; v2 *= sb; v3 *= sb;
                __half2 pa2 = __floats2half2_rn(v0, v1);
                __half2 pb2 = __floats2half2_rn(v2, v3);
                if (ra < M) C16[(size_t)ra * 64 + (col >> 1)] = *(uint32_t*)&pa2;
                if (rb < M) C16[(size_t)rb * 64 + (col >> 1)] = *(uint32_t*)&pb2;
            } else {
                if (ra < M) *(float2*)&C[(size_t)ra * 128 + col] = make_float2(v0, v1);
                if (rb < M) *(float2*)&C[(size_t)rb * 128 + col] = make_float2(v2, v3);
            }
        }
    }
}

#define SM_GEMM_TOTAL (4 * TILEW * 4 + 128 * 4)   // ~74 KB

// ---------------- fused CSR gather (fp16 xs) + skip + LayerNorm: warp per node ----------------
__global__ __launch_bounds__(256)
void k_gln(const uint32_t* __restrict__ xs16, float* __restrict__ h,
           const float* __restrict__ scale, const float* __restrict__ offset) {
    int node = (blockIdx.x * blockDim.x + threadIdx.x) >> 5;
    int lane = threadIdx.x & 31;
    if (node >= N_NODES) return;
    const int c = lane * 4;        // float columns
    const int w = lane * 2;        // half2 word index within row (64 words)

    float4 acc;
    {
        uint2 sv = *(const uint2*)&xs16[(size_t)node * 64 + w];   // self-loop
        float2 f0 = __half22float2(*(__half2*)&sv.x);
        float2 f1 = __half22float2(*(__half2*)&sv.y);
        acc = make_float4(f0.x, f0.y, f1.x, f1.y);
    }
    const int beg = g_start[node];
    const int end = beg + g_cr[node];

    for (int base = beg; base < end; base += 32) {
        int idx = (base + lane < end) ? g_csr[base + lane] : 0;
        int m = min(32, end - base);
        int j = 0;
        for (; j + 4 <= m; j += 4) {
            int s0 = __shfl_sync(0xffffffffu, idx, j);
            int s1 = __shfl_sync(0xffffffffu, idx, j + 1);
            int s2 = __shfl_sync(0xffffffffu, idx, j + 2);
            int s3 = __shfl_sync(0xffffffffu, idx, j + 3);
            uint2 v0 = *(const uint2*)&xs16[(size_t)s0 * 64 + w];
            uint2 v1 = *(const uint2*)&xs16[(size_t)s1 * 64 + w];
            uint2 v2 = *(const uint2*)&xs16[(size_t)s2 * 64 + w];
            uint2 v3 = *(const uint2*)&xs16[(size_t)s3 * 64 + w];
            __half2 hs0 = __hadd2(*(__half2*)&v0.x, *(__half2*)&v1.x);
            __half2 hs1 = __hadd2(*(__half2*)&v2.x, *(__half2*)&v3.x);
            __half2 ht0 = __hadd2(*(__half2*)&v0.y, *(__half2*)&v1.y);
            __half2 ht1 = __hadd2(*(__half2*)&v2.y, *(__half2*)&v3.y);
            float2 a0 = __half22float2(*(__half2*)&v0.x);
            // accumulate in fp32 (avoid fp16 accumulation error): expand each
            float2 e;
            e = __half22float2(*(__half2*)&v0.x); acc.x += e.x; acc.y += e.y;
            e = __half22float2(*(__half2*)&v1.x); acc.x += e.x; acc.y += e.y;
            e = __half22float2(*(__half2*)&v2.x); acc.x += e.x; acc.y += e.y;
            e = __half22float2(*(__half2*)&v3.x); acc.x += e.x; acc.y += e.y;
            e = __half22float2(*(__half2*)&v0.y); acc.z += e.x; acc.w += e.y;
            e = __half22float2(*(__half2*)&v1.y); acc.z += e.x; acc.w += e.y;
            e = __half22float2(*(__half2*)&v2.y); acc.z += e.x; acc.w += e.y;
            e = __half22float2(*(__half2*)&v3.y); acc.z += e.x; acc.w += e.y;
            (void)hs0; (void)hs1; (void)ht0; (void)ht1; (void)a0;
        }
        for (; j < m; j++) {
            int s = __shfl_sync(0xffffffffu, idx, j);
            uint2 v = *(const uint2*)&xs16[(size_t)s * 64 + w];
            float2 f0 = __half22float2(*(__half2*)&v.x);
            float2 f1 = __half22float2(*(__half2*)&v.y);
            acc.x += f0.x; acc.y += f0.y; acc.z += f1.x; acc.w += f1.y;
        }
    }

    float ir = g_invr[node];
    float4 vh = *(const float4*)&h[(size_t)node * 128 + c];
    float4 y;
    y.x = acc.x * ir + vh.x; y.y = acc.y * ir + vh.y;
    y.z = acc.z * ir + vh.z; y.w = acc.w * ir + vh.w;

    float sum = y.x + y.y + y.z + y.w;
    float sq  = y.x * y.x + y.y * y.y + y.z * y.z + y.w * y.w;
#pragma unroll
    for (int o = 16; o; o >>= 1) {
        sum += __shfl_xor_sync(0xffffffffu, sum, o);
        sq  += __shfl_xor_sync(0xffffffffu, sq, o);
    }
    float mean = sum * (1.f / 128.f);
    float var  = sq * (1.f / 128.f) - mean * mean;
    float rs = rsqrtf(var + LN_EPS);
    float4 scv = *(const float4*)&scale[c];
    float4 ofv = *(const float4*)&offset[c];
    y.x = (y.x - mean) * rs * scv.x + ofv.x;
    y.y = (y.y - mean) * rs * scv.y + ofv.y;
    y.z = (y.z - mean) * rs * scv.z + ofv.z;
    y.w = (y.w - mean) * rs * scv.w + ofv.w;
    *(float4*)&h[(size_t)node * 128 + c] = y;
}

// ---------------- pool (segment mean, contiguous 1000-node graphs) + decode ----------------
__global__ __launch_bounds__(128)
void k_pool(const float* __restrict__ dec_w, const float* __restrict__ dec_b,
            float* __restrict__ out) {
    int g = blockIdx.x;
    int c = threadIdx.x;
    const int per = N_NODES / N_GRAPH;
    const float* base = g_h + (size_t)g * per * 128;
    float sum = 0.f;
#pragma unroll 8
    for (int r = 0; r < per; r++) sum += base[(size_t)r * 128 + c];
    float val = (sum * (1.f / (float)per)) * dec_w[c];
    __shared__ float red[4];
#pragma unroll
    for (int o = 16; o; o >>= 1) val += __shfl_xor_sync(0xffffffffu, val, o);
    if ((threadIdx.x & 31) == 0) red[threadIdx.x >> 5] = val;
    __syncthreads();
    if (threadIdx.x == 0) out[g] = red[0] + red[1] + red[2] + red[3] + dec_b[0];
}

// ---------------- launch ----------------
extern "C" void kernel_launch(void* const* d_in, const int* in_sizes, int n_in,
                              void* d_out, int out_size) {
    const float* nodes     = (const float*)d_in[0];
    const int*   senders   = (const int*)d_in[1];
    const int*   receivers = (const int*)d_in[2];
    const float* embed_w   = (const float*)d_in[4];
    const float* embed_b   = (const float*)d_in[5];
    const float* mlp_w     = (const float*)d_in[6];
    const float* mlp_b     = (const float*)d_in[7];
    const float* ln_scale  = (const float*)d_in[8];
    const float* ln_offset = (const float*)d_in[9];
    const float* dec_w     = (const float*)d_in[10];
    const float* dec_b     = (const float*)d_in[11];
    float* out = (float*)d_out;

    float *ph, *pa;
    uint32_t *px16, *pwhi, *pwlo;
    cudaGetSymbolAddress((void**)&ph, g_h);
    cudaGetSymbolAddress((void**)&pa, g_a);
    cudaGetSymbolAddress((void**)&px16, g_x16);
    cudaGetSymbolAddress((void**)&pwhi, g_whi);
    cudaGetSymbolAddress((void**)&pwlo, g_wlo);

    cudaFuncSetAttribute(k_gemm_h2<64, 0>,  cudaFuncAttributeMaxDynamicSharedMemorySize, SM_GEMM_TOTAL);
    cudaFuncSetAttribute(k_gemm_h2<128, 1>, cudaFuncAttributeMaxDynamicSharedMemorySize, SM_GEMM_TOTAL);
    cudaFuncSetAttribute(k_gemm_h2<128, 2>, cudaFuncAttributeMaxDynamicSharedMemorySize, SM_GEMM_TOTAL);

    static cudaStream_t s2 = nullptr;
    static cudaEvent_t evFork = nullptr, evJoin = nullptr;
    if (!s2) {
        cudaStreamCreateWithFlags(&s2, cudaStreamNonBlocking);
        cudaEventCreateWithFlags(&evFork, cudaEventDisableTiming);
        cudaEventCreateWithFlags(&evJoin, cudaEventDisableTiming);
    }

    // ---- fork: CSR build on s2, GEMM front on main stream ----
    cudaEventRecord(evFork, 0);
    cudaStreamWaitEvent(s2, evFork, 0);
    k_zero_deg<<<(N_NODES + 255) / 256, 256, 0, s2>>>();
    k_count<<<(N_EDGES + 255) / 256, 256, 0, s2>>>(senders, receivers);
    k_inv<<<(N_NODES + 255) / 256, 256, 0, s2>>>();
    k_fill<<<(N_EDGES + 255) / 256, 256, 0, s2>>>(senders, receivers);
    cudaEventRecord(evJoin, s2);

    const int gemm_grid = (N_NODES + 127) / 128;

    k_wconv<<<(WCONV_WORDS + 255) / 256, 256>>>(embed_w, mlp_w);
    k_gemm_h2<64, 0><<<gemm_grid, 512, SM_GEMM_TOTAL>>>(nodes, pwhi, pwlo, embed_b, ph, nullptr, N_NODES);

    const uint32_t* whi_mlp[4];
    const uint32_t* wlo_mlp[4];
    for (int g = 0; g < 4; g++) {
        whi_mlp[g] = pwhi + 4096 + g * 8192;
        wlo_mlp[g] = pwlo + 4096 + g * 8192;
    }

    const int row_grid = (N_NODES * 32 + 255) / 256;
    bool joined = false;

    for (int s = 0; s < 2; s++) {
        const float* b0 = mlp_b + (size_t)(s * 2 + 0) * LATENT;
        const float* b1 = mlp_b + (size_t)(s * 2 + 1) * LATENT;

        // hidden = relu(h @ W0 + b0)
        k_gemm_h2<128, 1><<<gemm_grid, 512, SM_GEMM_TOTAL>>>(ph, whi_mlp[s * 2], wlo_mlp[s * 2], b0, pa, nullptr, N_NODES);
        if (!joined) {
            cudaStreamWaitEvent(0, evJoin, 0);
            joined = true;
        }
        // xs (half2) = relu(hidden @ W1 + b1) * inv_sqrt_sdeg
        k_gemm_h2<128, 2><<<gemm_grid, 512, SM_GEMM_TOTAL>>>(pa, whi_mlp[s * 2 + 1], wlo_mlp[s * 2 + 1], b1, nullptr, px16, N_NODES);
        // h = LN((xs[self] + sum_in xs) * inv_sqrt_rdeg + h)
        k_gln<<<row_grid, 256>>>(px16, ph, ln_scale + s * LATENT, ln_offset + s * LATENT);
    }

    k_pool<<<N_GRAPH, 128>>>(dec_w, dec_b, out);
}

// round 8
// speedup vs baseline: 3.2265x; 1.0428x over previous
#include <cuda_runtime.h>
#include <cuda_fp16.h>
#include <cstdint>

#define N_NODES 100000
#define N_EDGES 1600000
#define N_GRAPH 100
#define IN_DIM 64
#define LATENT 128
#define LN_EPS 1e-5f

// ---------------- scratch (device globals; no allocation allowed) ----------------
__device__ float    g_h[(size_t)N_NODES * LATENT];   // node state (fp32)
__device__ uint32_t g_hid16[(size_t)N_NODES * 64];   // mlp hidden, packed half2
__device__ uint32_t g_x16[(size_t)N_NODES * 64];     // xs, packed half2
__device__ int   g_cs[N_NODES];
__device__ int   g_cr[N_NODES];
__device__ float g_invs[N_NODES];
__device__ float g_invr[N_NODES];
__device__ int   g_start[N_NODES];
__device__ int   g_fill[N_NODES];
__device__ int   g_csr[N_EDGES];
__device__ int   g_cursor;
#define WCONV_WORDS (4096 + 4 * 8192)
__device__ uint32_t g_whi[WCONV_WORDS];
__device__ uint32_t g_wlo[WCONV_WORDS];

// ---------------- degree / CSR kernels ----------------
__global__ void k_zero_deg() {
    int i = blockIdx.x * blockDim.x + threadIdx.x;
    if (i < N_NODES) { g_cs[i] = 0; g_cr[i] = 0; }
    if (i == 0) g_cursor = 0;
}
__global__ void k_count(const int* __restrict__ senders, const int* __restrict__ receivers) {
    int e = blockIdx.x * blockDim.x + threadIdx.x;
    if (e < N_EDGES) {
        atomicAdd(&g_cs[senders[e]], 1);
        atomicAdd(&g_cr[receivers[e]], 1);
    }
}
__global__ void k_inv() {
    int i = blockIdx.x * blockDim.x + threadIdx.x;
    if (i < N_NODES) {
        g_invs[i] = rsqrtf((float)(g_cs[i] + 1));
        g_invr[i] = rsqrtf((float)(g_cr[i] + 1));
        int st = atomicAdd(&g_cursor, g_cr[i]);
        g_start[i] = st;
        g_fill[i] = st;
    }
}
__global__ void k_fill(const int* __restrict__ senders, const int* __restrict__ receivers) {
    int e = blockIdx.x * blockDim.x + threadIdx.x;
    if (e < N_EDGES) {
        int r = receivers[e];
        int pos = atomicAdd(&g_fill[r], 1);
        g_csr[pos] = senders[e];
    }
}

// ---------------- fp16 helpers ----------------
__device__ __forceinline__ void hilo(float x, __half& h, float& res) {
    h = __float2half_rn(x);
    res = x - __half2float(h);
}
__device__ __forceinline__ uint32_t pack2(__half a, __half b) {
    __half2 h = __halves2half2(a, b);
    return *(uint32_t*)&h;
}
__device__ __forceinline__ void mma_f16(float c[4], const uint32_t a[4],
                                        uint32_t b0, uint32_t b1) {
    asm volatile(
        "mma.sync.aligned.m16n8k16.row.col.f32.f16.f16.f32 "
        "{%0,%1,%2,%3}, {%4,%5,%6,%7}, {%8,%9}, {%0,%1,%2,%3};"
        : "+f"(c[0]), "+f"(c[1]), "+f"(c[2]), "+f"(c[3])
        : "r"(a[0]), "r"(a[1]), "r"(a[2]), "r"(a[3]),
          "r"(b0), "r"(b1));
}

// ---------------- weight pre-conversion ----------------
__global__ void k_wconv(const float* __restrict__ embed_w, const float* __restrict__ mlp_w) {
    int i = blockIdx.x * blockDim.x + threadIdx.x;
    if (i >= WCONV_WORDS) return;
    float v0, v1;
    if (i < 4096) {
        int n = i >> 5, kp = i & 31;
        v0 = embed_w[(size_t)(2 * kp) * 128 + n];
        v1 = embed_w[(size_t)(2 * kp + 1) * 128 + n];
    } else {
        int j = i - 4096;
        int g = j >> 13;
        int r = j & 8191;
        int n = r >> 6, kp = r & 63;
        const float* W = mlp_w + (size_t)g * 128 * 128;
        v0 = W[(size_t)(2 * kp) * 128 + n];
        v1 = W[(size_t)(2 * kp + 1) * 128 + n];
    }
    __half h0, h1; float r0, r1;
    hilo(v0, h0, r0); hilo(v1, h1, r1);
    g_whi[i] = pack2(h0, h1);
    g_wlo[i] = pack2(__float2half_rn(r0), __float2half_rn(r1));
}

// ---------------- warp-MMA fp16 GEMM ----------------
// MODE 0: +bias  MODE 1: +bias,relu  MODE 2: +bias,relu,*g_invs[row]
// AH16: A is packed half2 (single-precision pass dropped -> 2 MMA passes)
// OUT16: write packed half2 to C16 instead of fp32 C
#define S2 36
#define TILEW (128 * S2)

template<int KTOT, int MODE, bool AH16, bool OUT16>
__global__ __launch_bounds__(512, 2)
void k_gemm(const float* __restrict__ A, const uint32_t* __restrict__ A16,
            const uint32_t* __restrict__ Whi, const uint32_t* __restrict__ Wlo,
            const float* __restrict__ bias, float* __restrict__ C,
            uint32_t* __restrict__ C16, int M) {
    extern __shared__ uint32_t sm[];
    uint32_t* sAhi = sm;                      // always
    uint32_t* sBhi = sm + TILEW;
    uint32_t* sBlo = sm + 2 * TILEW;
    uint32_t* sAlo = sm + 3 * TILEW;          // only when !AH16
    float*    sBias = (float*)(sm + (AH16 ? 3 : 4) * TILEW);

    const int tid  = threadIdx.x;
    const int lane = tid & 31;
    const int wid  = tid >> 5;
    const int grp  = lane >> 2;
    const int tig  = lane & 3;
    const int wm   = wid & 3;
    const int wn   = wid >> 2;
    const int row0 = blockIdx.x * 128;
    const int WPR  = KTOT / 2;

    if (tid < 128) sBias[tid] = bias[tid];

    float acc[2][4][4];
#pragma unroll
    for (int i = 0; i < 2; i++)
#pragma unroll
        for (int j = 0; j < 4; j++)
#pragma unroll
            for (int q = 0; q < 4; q++) acc[i][j][q] = 0.f;

    const int n_chunks = KTOT / 64;
    for (int ch = 0; ch < n_chunks; ch++) {
        if (ch) __syncthreads();
        // ---- stage A chunk [128 rows x 64 k] ----
        if (AH16) {
            // plain copy of packed half2 words: 4096 words = 1024 uint4
#pragma unroll
            for (int it = 0; it < 2; it++) {
                int i = tid + it * 512;
                int r = i >> 3;
                int q = (i & 7) * 4;
                uint4 v = make_uint4(0, 0, 0, 0);
                if (row0 + r < M)
                    v = *(const uint4*)&A16[(size_t)(row0 + r) * (KTOT / 2) + ch * 32 + q];
                *(uint4*)&sAhi[r * S2 + q] = v;
            }
        } else {
#pragma unroll
            for (int it = 0; it < 4; it++) {
                int i  = tid + it * 512;
                int r  = i >> 4;
                int c4 = (i & 15) * 4;
                float4 v = make_float4(0.f, 0.f, 0.f, 0.f);
                if (row0 + r < M)
                    v = *(const float4*)&A[(size_t)(row0 + r) * KTOT + ch * 64 + c4];
                __half h0, h1, h2, h3; float r0, r1, r2, r3;
                hilo(v.x, h0, r0); hilo(v.y, h1, r1);
                hilo(v.z, h2, r2); hilo(v.w, h3, r3);
                int w = r * S2 + (c4 >> 1);
                *(uint2*)&sAhi[w] = make_uint2(pack2(h0, h1), pack2(h2, h3));
                *(uint2*)&sAlo[w] = make_uint2(
                    pack2(__float2half_rn(r0), __float2half_rn(r1)),
                    pack2(__float2half_rn(r2), __float2half_rn(r3)));
            }
        }
        // ---- stage B chunk: copy pre-converted words ----
#pragma unroll
        for (int it = 0; it < 2; it++) {
            int i = tid + it * 512;
            int n = i >> 3;
            int q = (i & 7) * 4;
            int gw = n * WPR + ch * 32 + q;
            int sw = n * S2 + q;
            *(uint4*)&sBhi[sw] = *(const uint4*)&Whi[gw];
            *(uint4*)&sBlo[sw] = *(const uint4*)&Wlo[gw];
        }
        __syncthreads();

#pragma unroll
        for (int ks = 0; ks < 4; ks++) {
            const int kb = ks * 8;
            uint32_t aH[2][4], aL[2][4];
#pragma unroll
            for (int mt = 0; mt < 2; mt++) {
                int base = (wm * 32 + mt * 16 + grp) * S2 + kb + tig;
                aH[mt][0] = sAhi[base];
                aH[mt][1] = sAhi[base + 8 * S2];
                aH[mt][2] = sAhi[base + 4];
                aH[mt][3] = sAhi[base + 8 * S2 + 4];
                if (!AH16) {
                    aL[mt][0] = sAlo[base];
                    aL[mt][1] = sAlo[base + 8 * S2];
                    aL[mt][2] = sAlo[base + 4];
                    aL[mt][3] = sAlo[base + 8 * S2 + 4];
                }
            }
#pragma unroll
            for (int nt = 0; nt < 4; nt++) {
                int bb = (wn * 32 + nt * 8 + grp) * S2 + kb + tig;
                uint32_t bh0 = sBhi[bb], bh1 = sBhi[bb + 4];
                uint32_t bl0 = sBlo[bb], bl1 = sBlo[bb + 4];
#pragma unroll
                for (int mt = 0; mt < 2; mt++) {
                    mma_f16(acc[mt][nt], aH[mt], bh0, bh1);
                    mma_f16(acc[mt][nt], aH[mt], bl0, bl1);
                    if (!AH16) mma_f16(acc[mt][nt], aL[mt], bh0, bh1);
                }
            }
        }
    }

#pragma unroll
    for (int mt = 0; mt < 2; mt++) {
        int ra = row0 + wm * 32 + mt * 16 + grp;
        int rb = ra + 8;
        float sa = 1.f, sb = 1.f;
        if (MODE == 2) {
            if (ra < M) sa = g_invs[ra];
            if (rb < M) sb = g_invs[rb];
        }
#pragma unroll
        for (int nt = 0; nt < 4; nt++) {
            int col = wn * 32 + nt * 8 + 2 * tig;
            float b0 = sBias[col], b1 = sBias[col + 1];
            float v0 = acc[mt][nt][0] + b0;
            float v1 = acc[mt][nt][1] + b1;
            float v2 = acc[mt][nt][2] + b0;
            float v3 = acc[mt][nt][3] + b1;
            if (MODE >= 1) {
                v0 = fmaxf(v0, 0.f); v1 = fmaxf(v1, 0.f);
                v2 = fmaxf(v2, 0.f); v3 = fmaxf(v3, 0.f);
            }
            if (MODE == 2) { v0 *= sa; v1 *= sa; v2 *= sb; v3 *= sb; }
            if (OUT16) {
                __half2 pa2 = __floats2half2_rn(v0, v1);
                __half2 pb2 = __floats2half2_rn(v2, v3);
                if (ra < M) C16[(size_t)ra * 64 + (col >> 1)] = *(uint32_t*)&pa2;
                if (rb < M) C16[(size_t)rb * 64 + (col >> 1)] = *(uint32_t*)&pb2;
            } else {
                if (ra < M) *(float2*)&C[(size_t)ra * 128 + col] = make_float2(v0, v1);
                if (rb < M) *(float2*)&C[(size_t)rb * 128 + col] = make_float2(v2, v3);
            }
        }
    }
}

#define SM_A32 (4 * TILEW * 4 + 128 * 4)   // ~74 KB
#define SM_A16 (3 * TILEW * 4 + 128 * 4)   // ~56 KB

// ---------------- fused CSR gather (fp16 xs) + skip + LayerNorm: warp per node ----------------
__global__ __launch_bounds__(256)
void k_gln(const uint32_t* __restrict__ xs16, float* __restrict__ h,
           const float* __restrict__ scale, const float* __restrict__ offset) {
    int node = (blockIdx.x * blockDim.x + threadIdx.x) >> 5;
    int lane = threadIdx.x & 31;
    if (node >= N_NODES) return;
    const int c = lane * 4;
    const int w = lane * 2;

    float4 acc;
    {
        uint2 sv = *(const uint2*)&xs16[(size_t)node * 64 + w];
        float2 f0 = __half22float2(*(__half2*)&sv.x);
        float2 f1 = __half22float2(*(__half2*)&sv.y);
        acc = make_float4(f0.x, f0.y, f1.x, f1.y);
    }
    const int beg = g_start[node];
    const int end = beg + g_cr[node];

    for (int base = beg; base < end; base += 32) {
        int idx = (base + lane < end) ? g_csr[base + lane] : 0;
        int m = min(32, end - base);
        int j = 0;
        for (; j + 4 <= m; j += 4) {
            int s0 = __shfl_sync(0xffffffffu, idx, j);
            int s1 = __shfl_sync(0xffffffffu, idx, j + 1);
            int s2 = __shfl_sync(0xffffffffu, idx, j + 2);
            int s3 = __shfl_sync(0xffffffffu, idx, j + 3);
            uint2 v0 = *(const uint2*)&xs16[(size_t)s0 * 64 + w];
            uint2 v1 = *(const uint2*)&xs16[(size_t)s1 * 64 + w];
            uint2 v2 = *(const uint2*)&xs16[(size_t)s2 * 64 + w];
            uint2 v3 = *(const uint2*)&xs16[(size_t)s3 * 64 + w];
            float2 e;
            e = __half22float2(*(__half2*)&v0.x); acc.x += e.x; acc.y += e.y;
            e = __half22float2(*(__half2*)&v1.x); acc.x += e.x; acc.y += e.y;
            e = __half22float2(*(__half2*)&v2.x); acc.x += e.x; acc.y += e.y;
            e = __half22float2(*(__half2*)&v3.x); acc.x += e.x; acc.y += e.y;
            e = __half22float2(*(__half2*)&v0.y); acc.z += e.x; acc.w += e.y;
            e = __half22float2(*(__half2*)&v1.y); acc.z += e.x; acc.w += e.y;
            e = __half22float2(*(__half2*)&v2.y); acc.z += e.x; acc.w += e.y;
            e = __half22float2(*(__half2*)&v3.y); acc.z += e.x; acc.w += e.y;
        }
        for (; j < m; j++) {
            int s = __shfl_sync(0xffffffffu, idx, j);
            uint2 v = *(const uint2*)&xs16[(size_t)s * 64 + w];
            float2 f0 = __half22float2(*(__half2*)&v.x);
            float2 f1 = __half22float2(*(__half2*)&v.y);
            acc.x += f0.x; acc.y += f0.y; acc.z += f1.x; acc.w += f1.y;
        }
    }

    float ir = g_invr[node];
    float4 vh = *(const float4*)&h[(size_t)node * 128 + c];
    float4 y;
    y.x = acc.x * ir + vh.x; y.y = acc.y * ir + vh.y;
    y.z = acc.z * ir + vh.z; y.w = acc.w * ir + vh.w;

    float sum = y.x + y.y + y.z + y.w;
    float sq  = y.x * y.x + y.y * y.y + y.z * y.z + y.w * y.w;
#pragma unroll
    for (int o = 16; o; o >>= 1) {
        sum += __shfl_xor_sync(0xffffffffu, sum, o);
        sq  += __shfl_xor_sync(0xffffffffu, sq, o);
    }
    float mean = sum * (1.f / 128.f);
    float var  = sq * (1.f / 128.f) - mean * mean;
    float rs = rsqrtf(var + LN_EPS);
    float4 scv = *(const float4*)&scale[c];
    float4 ofv = *(const float4*)&offset[c];
    y.x = (y.x - mean) * rs * scv.x + ofv.x;
    y.y = (y.y - mean) * rs * scv.y + ofv.y;
    y.z = (y.z - mean) * rs * scv.z + ofv.z;
    y.w = (y.w - mean) * rs * scv.w + ofv.w;
    *(float4*)&h[(size_t)node * 128 + c] = y;
}

// ---------------- pool + decode ----------------
__global__ __launch_bounds__(128)
void k_pool(const float* __restrict__ dec_w, const float* __restrict__ dec_b,
            float* __restrict__ out) {
    int g = blockIdx.x;
    int c = threadIdx.x;
    const int per = N_NODES / N_GRAPH;
    const float* base = g_h + (size_t)g * per * 128;
    float sum = 0.f;
#pragma unroll 8
    for (int r = 0; r < per; r++) sum += base[(size_t)r * 128 + c];
    float val = (sum * (1.f / (float)per)) * dec_w[c];
    __shared__ float red[4];
#pragma unroll
    for (int o = 16; o; o >>= 1) val += __shfl_xor_sync(0xffffffffu, val, o);
    if ((threadIdx.x & 31) == 0) red[threadIdx.x >> 5] = val;
    __syncthreads();
    if (threadIdx.x == 0) out[g] = red[0] + red[1] + red[2] + red[3] + dec_b[0];
}

// ---------------- launch ----------------
extern "C" void kernel_launch(void* const* d_in, const int* in_sizes, int n_in,
                              void* d_out, int out_size) {
    const float* nodes     = (const float*)d_in[0];
    const int*   senders   = (const int*)d_in[1];
    const int*   receivers = (const int*)d_in[2];
    const float* embed_w   = (const float*)d_in[4];
    const float* embed_b   = (const float*)d_in[5];
    const float* mlp_w     = (const float*)d_in[6];
    const float* mlp_b     = (const float*)d_in[7];
    const float* ln_scale  = (const float*)d_in[8];
    const float* ln_offset = (const float*)d_in[9];
    const float* dec_w     = (const float*)d_in[10];
    const float* dec_b     = (const float*)d_in[11];
    float* out = (float*)d_out;

    float *ph;
    uint32_t *phid16, *px16, *pwhi, *pwlo;
    cudaGetSymbolAddress((void**)&ph, g_h);
    cudaGetSymbolAddress((void**)&phid16, g_hid16);
    cudaGetSymbolAddress((void**)&px16, g_x16);
    cudaGetSymbolAddress((void**)&pwhi, g_whi);
    cudaGetSymbolAddress((void**)&pwlo, g_wlo);

    cudaFuncSetAttribute((const void*)k_gemm<64, 0, false, false>, cudaFuncAttributeMaxDynamicSharedMemorySize, SM_A32);
    cudaFuncSetAttribute((const void*)k_gemm<128, 1, false, true>, cudaFuncAttributeMaxDynamicSharedMemorySize, SM_A32);
    cudaFuncSetAttribute((const void*)k_gemm<128, 2, true, true>,  cudaFuncAttributeMaxDynamicSharedMemorySize, SM_A16);

    static cudaStream_t s2 = nullptr;
    static cudaEvent_t evFork = nullptr, evJoin = nullptr;
    if (!s2) {
        cudaStreamCreateWithFlags(&s2, cudaStreamNonBlocking);
        cudaEventCreateWithFlags(&evFork, cudaEventDisableTiming);
        cudaEventCreateWithFlags(&evJoin, cudaEventDisableTiming);
    }

    // ---- fork: CSR build on s2 ----
    cudaEventRecord(evFork, 0);
    cudaStreamWaitEvent(s2, evFork, 0);
    k_zero_deg<<<(N_NODES + 255) / 256, 256, 0, s2>>>();
    k_count<<<(N_EDGES + 255) / 256, 256, 0, s2>>>(senders, receivers);
    k_inv<<<(N_NODES + 255) / 256, 256, 0, s2>>>();
    k_fill<<<(N_EDGES + 255) / 256, 256, 0, s2>>>(senders, receivers);
    cudaEventRecord(evJoin, s2);

    const int gemm_grid = (N_NODES + 127) / 128;

    k_wconv<<<(WCONV_WORDS + 255) / 256, 256>>>(embed_w, mlp_w);
    k_gemm<64, 0, false, false><<<gemm_grid, 512, SM_A32>>>(nodes, nullptr, pwhi, pwlo, embed_b, ph, nullptr, N_NODES);

    const uint32_t* whi_mlp[4];
    const uint32_t* wlo_mlp[4];
    for (int g = 0; g < 4; g++) {
        whi_mlp[g] = pwhi + 4096 + g * 8192;
        wlo_mlp[g] = pwlo + 4096 + g * 8192;
    }

    const int row_grid = (N_NODES * 32 + 255) / 256;
    bool joined = false;

    for (int s = 0; s < 2; s++) {
        const float* b0 = mlp_b + (size_t)(s * 2 + 0) * LATENT;
        const float* b1 = mlp_b + (size_t)(s * 2 + 1) * LATENT;

        // hidden (half2) = relu(h @ W0 + b0)
        k_gemm<128, 1, false, true><<<gemm_grid, 512, SM_A32>>>(ph, nullptr, whi_mlp[s * 2], wlo_mlp[s * 2], b0, nullptr, phid16, N_NODES);
        if (!joined) {
            cudaStreamWaitEvent(0, evJoin, 0);
            joined = true;
        }
        // xs (half2) = relu(hidden @ W1 + b1) * inv_sqrt_sdeg   (A in fp16, 2 MMA passes)
        k_gemm<128, 2, true, true><<<gemm_grid, 512, SM_A16>>>(nullptr, phid16, whi_mlp[s * 2 + 1], wlo_mlp[s * 2 + 1], b1, nullptr, px16, N_NODES);
        // h = LN((xs[self] + sum_in xs) * inv_sqrt_rdeg + h)
        k_gln<<<row_grid, 256>>>(px16, ph, ln_scale + s * LATENT, ln_offset + s * LATENT);
    }

    k_pool<<<N_GRAPH, 128>>>(dec_w, dec_b, out);
}

// round 9
// speedup vs baseline: 3.8713x; 1.1998x over previous
#include <cuda_runtime.h>
#include <cuda_fp16.h>
#include <cstdint>

#define N_NODES 100000
#define N_EDGES 1600000
#define N_GRAPH 100
#define IN_DIM 64
#define LATENT 128
#define LN_EPS 1e-5f

// ---------------- scratch (device globals; no allocation allowed) ----------------
__device__ uint32_t g_h16[(size_t)N_NODES * 64];     // node state, packed half2
__device__ uint32_t g_hid16[(size_t)N_NODES * 64];   // mlp hidden, packed half2
__device__ uint32_t g_x16[(size_t)N_NODES * 64];     // xs, packed half2
__device__ int   g_cs[N_NODES];
__device__ int   g_cr[N_NODES];
__device__ float g_invs[N_NODES];
__device__ float g_invr[N_NODES];
__device__ int   g_start[N_NODES];
__device__ int   g_fill[N_NODES];
__device__ int   g_csr[N_EDGES];
__device__ int   g_cursor;
#define WCONV_WORDS (4096 + 4 * 8192)
__device__ uint32_t g_whi[WCONV_WORDS];
__device__ uint32_t g_wlo[WCONV_WORDS];

// ---------------- degree / CSR kernels ----------------
__global__ void k_zero_deg() {
    int i = blockIdx.x * blockDim.x + threadIdx.x;
    if (i < N_NODES) { g_cs[i] = 0; g_cr[i] = 0; }
    if (i == 0) g_cursor = 0;
}
__global__ void k_count(const int* __restrict__ senders, const int* __restrict__ receivers) {
    int e = blockIdx.x * blockDim.x + threadIdx.x;
    if (e < N_EDGES) {
        atomicAdd(&g_cs[senders[e]], 1);
        atomicAdd(&g_cr[receivers[e]], 1);
    }
}
__global__ void k_inv() {
    int i = blockIdx.x * blockDim.x + threadIdx.x;
    if (i < N_NODES) {
        g_invs[i] = rsqrtf((float)(g_cs[i] + 1));
        g_invr[i] = rsqrtf((float)(g_cr[i] + 1));
        int st = atomicAdd(&g_cursor, g_cr[i]);
        g_start[i] = st;
        g_fill[i] = st;
    }
}
__global__ void k_fill(const int* __restrict__ senders, const int* __restrict__ receivers) {
    int e = blockIdx.x * blockDim.x + threadIdx.x;
    if (e < N_EDGES) {
        int r = receivers[e];
        int pos = atomicAdd(&g_fill[r], 1);
        g_csr[pos] = senders[e];
    }
}

// ---------------- fp16 helpers ----------------
__device__ __forceinline__ void hilo(float x, __half& h, float& res) {
    h = __float2half_rn(x);
    res = x - __half2float(h);
}
__device__ __forceinline__ uint32_t pack2(__half a, __half b) {
    __half2 h = __halves2half2(a, b);
    return *(uint32_t*)&h;
}
__device__ __forceinline__ void mma_f16(float c[4], const uint32_t a[4],
                                        uint32_t b0, uint32_t b1) {
    asm volatile(
        "mma.sync.aligned.m16n8k16.row.col.f32.f16.f16.f32 "
        "{%0,%1,%2,%3}, {%4,%5,%6,%7}, {%8,%9}, {%0,%1,%2,%3};"
        : "+f"(c[0]), "+f"(c[1]), "+f"(c[2]), "+f"(c[3])
        : "r"(a[0]), "r"(a[1]), "r"(a[2]), "r"(a[3]),
          "r"(b0), "r"(b1));
}

// ---------------- weight pre-conversion ----------------
__global__ void k_wconv(const float* __restrict__ embed_w, const float* __restrict__ mlp_w) {
    int i = blockIdx.x * blockDim.x + threadIdx.x;
    if (i >= WCONV_WORDS) return;
    float v0, v1;
    if (i < 4096) {
        int n = i >> 5, kp = i & 31;
        v0 = embed_w[(size_t)(2 * kp) * 128 + n];
        v1 = embed_w[(size_t)(2 * kp + 1) * 128 + n];
    } else {
        int j = i - 4096;
        int g = j >> 13;
        int r = j & 8191;
        int n = r >> 6, kp = r & 63;
        const float* W = mlp_w + (size_t)g * 128 * 128;
        v0 = W[(size_t)(2 * kp) * 128 + n];
        v1 = W[(size_t)(2 * kp + 1) * 128 + n];
    }
    __half h0, h1; float r0, r1;
    hilo(v0, h0, r0); hilo(v1, h1, r1);
    g_whi[i] = pack2(h0, h1);
    g_wlo[i] = pack2(__float2half_rn(r0), __float2half_rn(r1));
}

// ---------------- warp-MMA fp16 GEMM ----------------
// MODE 0: +bias  MODE 1: +bias,relu  MODE 2: +bias,relu,*g_invs[row]
// AH16: A is packed half2 (2 MMA passes)   output always packed half2
#define S2 36
#define TILEW (128 * S2)

template<int KTOT, int MODE, bool AH16>
__global__ __launch_bounds__(512, 2)
void k_gemm(const float* __restrict__ A, const uint32_t* __restrict__ A16,
            const uint32_t* __restrict__ Whi, const uint32_t* __restrict__ Wlo,
            const float* __restrict__ bias, uint32_t* __restrict__ C16, int M) {
    extern __shared__ uint32_t sm[];
    uint32_t* sAhi = sm;
    uint32_t* sBhi = sm + TILEW;
    uint32_t* sBlo = sm + 2 * TILEW;
    uint32_t* sAlo = sm + 3 * TILEW;          // only when !AH16
    float*    sBias = (float*)(sm + (AH16 ? 3 : 4) * TILEW);

    const int tid  = threadIdx.x;
    const int lane = tid & 31;
    const int wid  = tid >> 5;
    const int grp  = lane >> 2;
    const int tig  = lane & 3;
    const int wm   = wid & 3;
    const int wn   = wid >> 2;
    const int row0 = blockIdx.x * 128;
    const int WPR  = KTOT / 2;

    if (tid < 128) sBias[tid] = bias[tid];

    float acc[2][4][4];
#pragma unroll
    for (int i = 0; i < 2; i++)
#pragma unroll
        for (int j = 0; j < 4; j++)
#pragma unroll
            for (int q = 0; q < 4; q++) acc[i][j][q] = 0.f;

    const int n_chunks = KTOT / 64;
    for (int ch = 0; ch < n_chunks; ch++) {
        if (ch) __syncthreads();
        // ---- stage A chunk [128 rows x 64 k] ----
        if (AH16) {
#pragma unroll
            for (int it = 0; it < 2; it++) {
                int i = tid + it * 512;
                int r = i >> 3;
                int q = (i & 7) * 4;
                uint4 v = make_uint4(0, 0, 0, 0);
                if (row0 + r < M)
                    v = *(const uint4*)&A16[(size_t)(row0 + r) * (KTOT / 2) + ch * 32 + q];
                *(uint4*)&sAhi[r * S2 + q] = v;
            }
        } else {
#pragma unroll
            for (int it = 0; it < 4; it++) {
                int i  = tid + it * 512;
                int r  = i >> 4;
                int c4 = (i & 15) * 4;
                float4 v = make_float4(0.f, 0.f, 0.f, 0.f);
                if (row0 + r < M)
                    v = *(const float4*)&A[(size_t)(row0 + r) * KTOT + ch * 64 + c4];
                __half h0, h1, h2, h3; float r0, r1, r2, r3;
                hilo(v.x, h0, r0); hilo(v.y, h1, r1);
                hilo(v.z, h2, r2); hilo(v.w, h3, r3);
                int w = r * S2 + (c4 >> 1);
                *(uint2*)&sAhi[w] = make_uint2(pack2(h0, h1), pack2(h2, h3));
                *(uint2*)&sAlo[w] = make_uint2(
                    pack2(__float2half_rn(r0), __float2half_rn(r1)),
                    pack2(__float2half_rn(r2), __float2half_rn(r3)));
            }
        }
        // ---- stage B chunk ----
#pragma unroll
        for (int it = 0; it < 2; it++) {
            int i = tid + it * 512;
            int n = i >> 3;
            int q = (i & 7) * 4;
            int gw = n * WPR + ch * 32 + q;
            int sw = n * S2 + q;
            *(uint4*)&sBhi[sw] = *(const uint4*)&Whi[gw];
            *(uint4*)&sBlo[sw] = *(const uint4*)&Wlo[gw];
        }
        __syncthreads();

#pragma unroll
        for (int ks = 0; ks < 4; ks++) {
            const int kb = ks * 8;
            uint32_t aH[2][4], aL[2][4];
#pragma unroll
            for (int mt = 0; mt < 2; mt++) {
                int base = (wm * 32 + mt * 16 + grp) * S2 + kb + tig;
                aH[mt][0] = sAhi[base];
                aH[mt][1] = sAhi[base + 8 * S2];
                aH[mt][2] = sAhi[base + 4];
                aH[mt][3] = sAhi[base + 8 * S2 + 4];
                if (!AH16) {
                    aL[mt][0] = sAlo[base];
                    aL[mt][1] = sAlo[base + 8 * S2];
                    aL[mt][2] = sAlo[base + 4];
                    aL[mt][3] = sAlo[base + 8 * S2 + 4];
                }
            }
#pragma unroll
            for (int nt = 0; nt < 4; nt++) {
                int bb = (wn * 32 + nt * 8 + grp) * S2 + kb + tig;
                uint32_t bh0 = sBhi[bb], bh1 = sBhi[bb + 4];
                uint32_t bl0 = sBlo[bb], bl1 = sBlo[bb + 4];
#pragma unroll
                for (int mt = 0; mt < 2; mt++) {
                    mma_f16(acc[mt][nt], aH[mt], bh0, bh1);
                    mma_f16(acc[mt][nt], aH[mt], bl0, bl1);
                    if (!AH16) mma_f16(acc[mt][nt], aL[mt], bh0, bh1);
                }
            }
        }
    }

#pragma unroll
    for (int mt = 0; mt < 2; mt++) {
        int ra = row0 + wm * 32 + mt * 16 + grp;
        int rb = ra + 8;
        float sa = 1.f, sb = 1.f;
        if (MODE == 2) {
            if (ra < M) sa = g_invs[ra];
            if (rb < M) sb = g_invs[rb];
        }
#pragma unroll
        for (int nt = 0; nt < 4; nt++) {
            int col = wn * 32 + nt * 8 + 2 * tig;
            float b0 = sBias[col], b1 = sBias[col + 1];
            float v0 = acc[mt][nt][0] + b0;
            float v1 = acc[mt][nt][1] + b1;
            float v2 = acc[mt][nt][2] + b0;
            float v3 = acc[mt][nt][3] + b1;
            if (MODE >= 1) {
                v0 = fmaxf(v0, 0.f); v1 = fmaxf(v1, 0.f);
                v2 = fmaxf(v2, 0.f); v3 = fmaxf(v3, 0.f);
            }
            if (MODE == 2) { v0 *= sa; v1 *= sa; v2 *= sb; v3 *= sb; }
            __half2 pa2 = __floats2half2_rn(v0, v1);
            __half2 pb2 = __floats2half2_rn(v2, v3);
            if (ra < M) C16[(size_t)ra * 64 + (col >> 1)] = *(uint32_t*)&pa2;
            if (rb < M) C16[(size_t)rb * 64 + (col >> 1)] = *(uint32_t*)&pb2;
        }
    }
}

#define SM_A32 (4 * TILEW * 4 + 128 * 4)   // ~74 KB
#define SM_A16 (3 * TILEW * 4 + 128 * 4)   // ~56 KB

// ---------------- fused CSR gather (fp16) + skip + LayerNorm (fp16 h): warp per node ----------------
__global__ __launch_bounds__(256)
void k_gln(const uint32_t* __restrict__ xs16, uint32_t* __restrict__ h16,
           const float* __restrict__ scale, const float* __restrict__ offset) {
    int node = (blockIdx.x * blockDim.x + threadIdx.x) >> 5;
    int lane = threadIdx.x & 31;
    if (node >= N_NODES) return;
    const int c = lane * 4;        // float columns
    const int w = lane * 2;        // half2 words

    float4 acc;
    {
        uint2 sv = *(const uint2*)&xs16[(size_t)node * 64 + w];
        float2 f0 = __half22float2(*(__half2*)&sv.x);
        float2 f1 = __half22float2(*(__half2*)&sv.y);
        acc = make_float4(f0.x, f0.y, f1.x, f1.y);
    }
    const int beg = g_start[node];
    const int end = beg + g_cr[node];

    for (int base = beg; base < end; base += 32) {
        int idx = (base + lane < end) ? g_csr[base + lane] : 0;
        int m = min(32, end - base);
        int j = 0;
        for (; j + 4 <= m; j += 4) {
            int s0 = __shfl_sync(0xffffffffu, idx, j);
            int s1 = __shfl_sync(0xffffffffu, idx, j + 1);
            int s2 = __shfl_sync(0xffffffffu, idx, j + 2);
            int s3 = __shfl_sync(0xffffffffu, idx, j + 3);
            uint2 v0 = *(const uint2*)&xs16[(size_t)s0 * 64 + w];
            uint2 v1 = *(const uint2*)&xs16[(size_t)s1 * 64 + w];
            uint2 v2 = *(const uint2*)&xs16[(size_t)s2 * 64 + w];
            uint2 v3 = *(const uint2*)&xs16[(size_t)s3 * 64 + w];
            float2 e;
            e = __half22float2(*(__half2*)&v0.x); acc.x += e.x; acc.y += e.y;
            e = __half22float2(*(__half2*)&v1.x); acc.x += e.x; acc.y += e.y;
            e = __half22float2(*(__half2*)&v2.x); acc.x += e.x; acc.y += e.y;
            e = __half22float2(*(__half2*)&v3.x); acc.x += e.x; acc.y += e.y;
            e = __half22float2(*(__half2*)&v0.y); acc.z += e.x; acc.w += e.y;
            e = __half22float2(*(__half2*)&v1.y); acc.z += e.x; acc.w += e.y;
            e = __half22float2(*(__half2*)&v2.y); acc.z += e.x; acc.w += e.y;
            e = __half22float2(*(__half2*)&v3.y); acc.z += e.x; acc.w += e.y;
        }
        for (; j < m; j++) {
            int s = __shfl_sync(0xffffffffu, idx, j);
            uint2 v = *(const uint2*)&xs16[(size_t)s * 64 + w];
            float2 f0 = __half22float2(*(__half2*)&v.x);
            float2 f1 = __half22float2(*(__half2*)&v.y);
            acc.x += f0.x; acc.y += f0.y; acc.z += f1.x; acc.w += f1.y;
        }
    }

    float ir = g_invr[node];
    float4 vh;
    {
        uint2 hv = *(const uint2*)&h16[(size_t)node * 64 + w];
        float2 f0 = __half22float2(*(__half2*)&hv.x);
        float2 f1 = __half22float2(*(__half2*)&hv.y);
        vh = make_float4(f0.x, f0.y, f1.x, f1.y);
    }
    float4 y;
    y.x = acc.x * ir + vh.x; y.y = acc.y * ir + vh.y;
    y.z = acc.z * ir + vh.z; y.w = acc.w * ir + vh.w;

    float sum = y.x + y.y + y.z + y.w;
    float sq  = y.x * y.x + y.y * y.y + y.z * y.z + y.w * y.w;
#pragma unroll
    for (int o = 16; o; o >>= 1) {
        sum += __shfl_xor_sync(0xffffffffu, sum, o);
        sq  += __shfl_xor_sync(0xffffffffu, sq, o);
    }
    float mean = sum * (1.f / 128.f);
    float var  = sq * (1.f / 128.f) - mean * mean;
    float rs = rsqrtf(var + LN_EPS);
    float4 scv = *(const float4*)&scale[c];
    float4 ofv = *(const float4*)&offset[c];
    y.x = (y.x - mean) * rs * scv.x + ofv.x;
    y.y = (y.y - mean) * rs * scv.y + ofv.y;
    y.z = (y.z - mean) * rs * scv.z + ofv.z;
    y.w = (y.w - mean) * rs * scv.w + ofv.w;
    __half2 p0 = __floats2half2_rn(y.x, y.y);
    __half2 p1 = __floats2half2_rn(y.z, y.w);
    *(uint2*)&h16[(size_t)node * 64 + w] = make_uint2(*(uint32_t*)&p0, *(uint32_t*)&p1);
}

// ---------------- pool (fp16 h) + decode: 64 threads, one word each ----------------
__global__ __launch_bounds__(64)
void k_pool(const uint32_t* __restrict__ h16, const float* __restrict__ dec_w,
            const float* __restrict__ dec_b, float* __restrict__ out) {
    int g = blockIdx.x;
    int w = threadIdx.x;                  // 0..63 half2 words
    const int per = N_NODES / N_GRAPH;    // 1000
    const uint32_t* base = h16 + (size_t)g * per * 64;
    float s0 = 0.f, s1 = 0.f;
#pragma unroll 8
    for (int r = 0; r < per; r++) {
        uint32_t v = base[(size_t)r * 64 + w];
        float2 f = __half22float2(*(__half2*)&v);
        s0 += f.x; s1 += f.y;
    }
    float val = (s0 * dec_w[2 * w] + s1 * dec_w[2 * w + 1]) * (1.f / (float)per);
    __shared__ float red[2];
#pragma unroll
    for (int o = 16; o; o >>= 1) val += __shfl_xor_sync(0xffffffffu, val, o);
    if ((threadIdx.x & 31) == 0) red[threadIdx.x >> 5] = val;
    __syncthreads();
    if (threadIdx.x == 0) out[g] = red[0] + red[1] + dec_b[0];
}

// ---------------- launch ----------------
extern "C" void kernel_launch(void* const* d_in, const int* in_sizes, int n_in,
                              void* d_out, int out_size) {
    const float* nodes     = (const float*)d_in[0];
    const int*   senders   = (const int*)d_in[1];
    const int*   receivers = (const int*)d_in[2];
    const float* embed_w   = (const float*)d_in[4];
    const float* embed_b   = (const float*)d_in[5];
    const float* mlp_w     = (const float*)d_in[6];
    const float* mlp_b     = (const float*)d_in[7];
    const float* ln_scale  = (const float*)d_in[8];
    const float* ln_offset = (const float*)d_in[9];
    const float* dec_w     = (const float*)d_in[10];
    const float* dec_b     = (const float*)d_in[11];
    float* out = (float*)d_out;

    uint32_t *ph16, *phid16, *px16, *pwhi, *pwlo;
    cudaGetSymbolAddress((void**)&ph16, g_h16);
    cudaGetSymbolAddress((void**)&phid16, g_hid16);
    cudaGetSymbolAddress((void**)&px16, g_x16);
    cudaGetSymbolAddress((void**)&pwhi, g_whi);
    cudaGetSymbolAddress((void**)&pwlo, g_wlo);

    cudaFuncSetAttribute((const void*)k_gemm<64, 0, false>, cudaFuncAttributeMaxDynamicSharedMemorySize, SM_A32);
    cudaFuncSetAttribute((const void*)k_gemm<128, 1, true>, cudaFuncAttributeMaxDynamicSharedMemorySize, SM_A16);
    cudaFuncSetAttribute((const void*)k_gemm<128, 2, true>, cudaFuncAttributeMaxDynamicSharedMemorySize, SM_A16);

    static cudaStream_t s2 = nullptr;
    static cudaEvent_t evFork = nullptr, evJoin = nullptr;
    if (!s2) {
        cudaStreamCreateWithFlags(&s2, cudaStreamNonBlocking);
        cudaEventCreateWithFlags(&evFork, cudaEventDisableTiming);
        cudaEventCreateWithFlags(&evJoin, cudaEventDisableTiming);
    }

    // ---- fork: CSR build on s2 ----
    cudaEventRecord(evFork, 0);
    cudaStreamWaitEvent(s2, evFork, 0);
    k_zero_deg<<<(N_NODES + 255) / 256, 256, 0, s2>>>();
    k_count<<<(N_EDGES + 255) / 256, 256, 0, s2>>>(senders, receivers);
    k_inv<<<(N_NODES + 255) / 256, 256, 0, s2>>>();
    k_fill<<<(N_EDGES + 255) / 256, 256, 0, s2>>>(senders, receivers);
    cudaEventRecord(evJoin, s2);

    const int gemm_grid = (N_NODES + 127) / 128;

    k_wconv<<<(WCONV_WORDS + 255) / 256, 256>>>(embed_w, mlp_w);
    // embed: h16 = nodes @ embed_w + embed_b
    k_gemm<64, 0, false><<<gemm_grid, 512, SM_A32>>>(nodes, nullptr, pwhi, pwlo, embed_b, ph16, N_NODES);

    const uint32_t* whi_mlp[4];
    const uint32_t* wlo_mlp[4];
    for (int g = 0; g < 4; g++) {
        whi_mlp[g] = pwhi + 4096 + g * 8192;
        wlo_mlp[g] = pwlo + 4096 + g * 8192;
    }

    const int row_grid = (N_NODES * 32 + 255) / 256;
    bool joined = false;

    for (int s = 0; s < 2; s++) {
        const float* b0 = mlp_b + (size_t)(s * 2 + 0) * LATENT;
        const float* b1 = mlp_b + (size_t)(s * 2 + 1) * LATENT;

        // hidden = relu(h @ W0 + b0)   (A fp16, 2 passes)
        k_gemm<128, 1, true><<<gemm_grid, 512, SM_A16>>>(nullptr, ph16, whi_mlp[s * 2], wlo_mlp[s * 2], b0, phid16, N_NODES);
        if (!joined) {
            cudaStreamWaitEvent(0, evJoin, 0);
            joined = true;
        }
        // xs = relu(hidden @ W1 + b1) * inv_sqrt_sdeg   (A fp16, 2 passes)
        k_gemm<128, 2, true><<<gemm_grid, 512, SM_A16>>>(nullptr, phid16, whi_mlp[s * 2 + 1], wlo_mlp[s * 2 + 1], b1, px16, N_NODES);
        // h = LN((xs[self] + sum_in xs) * inv_sqrt_rdeg + h)
        k_gln<<<row_grid, 256>>>(px16, ph16, ln_scale + s * LATENT, ln_offset + s * LATENT);
    }

    k_pool<<<N_GRAPH, 64>>>(ph16, dec_w, dec_b, out);
}

// round 10
// speedup vs baseline: 4.2028x; 1.0856x over previous
#include <cuda_runtime.h>
#include <cuda_fp16.h>
#include <cstdint>

#define N_NODES 100000
#define N_EDGES 1600000
#define N_GRAPH 100
#define IN_DIM 64
#define LATENT 128
#define LN_EPS 1e-5f

// ---------------- scratch (device globals; no allocation allowed) ----------------
__device__ uint32_t g_h16[(size_t)N_NODES * 64];     // node state, packed half2
__device__ uint32_t g_x16[(size_t)N_NODES * 64];     // xs, packed half2
__device__ int   g_cs[N_NODES];
__device__ int   g_cr[N_NODES];
__device__ float g_invs[N_NODES];
__device__ float g_invr[N_NODES];
__device__ int   g_start[N_NODES];
__device__ int   g_fill[N_NODES];
__device__ int   g_csr[N_EDGES];
__device__ int   g_cursor;
#define WCONV_WORDS (4096 + 4 * 8192)
__device__ uint32_t g_whi[WCONV_WORDS];
__device__ uint32_t g_wlo[WCONV_WORDS];

// ---------------- degree / CSR kernels ----------------
__global__ void k_zero_deg() {
    int i = blockIdx.x * blockDim.x + threadIdx.x;
    if (i < N_NODES) { g_cs[i] = 0; g_cr[i] = 0; }
    if (i == 0) g_cursor = 0;
}
__global__ void k_count(const int* __restrict__ senders, const int* __restrict__ receivers) {
    int e = blockIdx.x * blockDim.x + threadIdx.x;
    if (e < N_EDGES) {
        atomicAdd(&g_cs[senders[e]], 1);
        atomicAdd(&g_cr[receivers[e]], 1);
    }
}
__global__ void k_inv() {
    int i = blockIdx.x * blockDim.x + threadIdx.x;
    if (i < N_NODES) {
        g_invs[i] = rsqrtf((float)(g_cs[i] + 1));
        g_invr[i] = rsqrtf((float)(g_cr[i] + 1));
        int st = atomicAdd(&g_cursor, g_cr[i]);
        g_start[i] = st;
        g_fill[i] = st;
    }
}
__global__ void k_fill(const int* __restrict__ senders, const int* __restrict__ receivers) {
    int e = blockIdx.x * blockDim.x + threadIdx.x;
    if (e < N_EDGES) {
        int r = receivers[e];
        int pos = atomicAdd(&g_fill[r], 1);
        g_csr[pos] = senders[e];
    }
}

// ---------------- fp16 helpers ----------------
__device__ __forceinline__ void hilo(float x, __half& h, float& res) {
    h = __float2half_rn(x);
    res = x - __half2float(h);
}
__device__ __forceinline__ uint32_t pack2(__half a, __half b) {
    __half2 h = __halves2half2(a, b);
    return *(uint32_t*)&h;
}
__device__ __forceinline__ void mma_f16(float c[4], const uint32_t a[4],
                                        uint32_t b0, uint32_t b1) {
    asm volatile(
        "mma.sync.aligned.m16n8k16.row.col.f32.f16.f16.f32 "
        "{%0,%1,%2,%3}, {%4,%5,%6,%7}, {%8,%9}, {%0,%1,%2,%3};"
        : "+f"(c[0]), "+f"(c[1]), "+f"(c[2]), "+f"(c[3])
        : "r"(a[0]), "r"(a[1]), "r"(a[2]), "r"(a[3]),
          "r"(b0), "r"(b1));
}

// ---------------- weight pre-conversion ----------------
__global__ void k_wconv(const float* __restrict__ embed_w, const float* __restrict__ mlp_w) {
    int i = blockIdx.x * blockDim.x + threadIdx.x;
    if (i >= WCONV_WORDS) return;
    float v0, v1;
    if (i < 4096) {
        int n = i >> 5, kp = i & 31;
        v0 = embed_w[(size_t)(2 * kp) * 128 + n];
        v1 = embed_w[(size_t)(2 * kp + 1) * 128 + n];
    } else {
        int j = i - 4096;
        int g = j >> 13;
        int r = j & 8191;
        int n = r >> 6, kp = r & 63;
        const float* W = mlp_w + (size_t)g * 128 * 128;
        v0 = W[(size_t)(2 * kp) * 128 + n];
        v1 = W[(size_t)(2 * kp + 1) * 128 + n];
    }
    __half h0, h1; float r0, r1;
    hilo(v0, h0, r0); hilo(v1, h1, r1);
    g_whi[i] = pack2(h0, h1);
    g_wlo[i] = pack2(__float2half_rn(r0), __float2half_rn(r1));
}

#define S2  36    // B chunk stride (words)
#define S2F 68    // A full-K stride (words)
#define TILEW (128 * S2)

// ---------------- embed GEMM: fp32 A, hi/lo split (3 passes), K=64 ----------------
__global__ __launch_bounds__(512, 2)
void k_embed(const float* __restrict__ A,
             const uint32_t* __restrict__ Whi, const uint32_t* __restrict__ Wlo,
             const float* __restrict__ bias, uint32_t* __restrict__ C16, int M) {
    extern __shared__ uint32_t sm[];
    uint32_t* sAhi = sm;
    uint32_t* sBhi = sm + TILEW;
    uint32_t* sBlo = sm + 2 * TILEW;
    uint32_t* sAlo = sm + 3 * TILEW;
    float*    sBias = (float*)(sm + 4 * TILEW);

    const int tid  = threadIdx.x;
    const int lane = tid & 31;
    const int wid  = tid >> 5;
    const int grp  = lane >> 2;
    const int tig  = lane & 3;
    const int wm   = wid & 3;
    const int wn   = wid >> 2;
    const int row0 = blockIdx.x * 128;

    if (tid < 128) sBias[tid] = bias[tid];

    float acc[2][4][4];
#pragma unroll
    for (int i = 0; i < 2; i++)
#pragma unroll
        for (int j = 0; j < 4; j++)
#pragma unroll
            for (int q = 0; q < 4; q++) acc[i][j][q] = 0.f;

    // stage A [128 x 64] fp32 -> fp16 hi/lo
#pragma unroll
    for (int it = 0; it < 4; it++) {
        int i  = tid + it * 512;
        int r  = i >> 4;
        int c4 = (i & 15) * 4;
        float4 v = make_float4(0.f, 0.f, 0.f, 0.f);
        if (row0 + r < M)
            v = *(const float4*)&A[(size_t)(row0 + r) * 64 + c4];
        __half h0, h1, h2, h3; float r0, r1, r2, r3;
        hilo(v.x, h0, r0); hilo(v.y, h1, r1);
        hilo(v.z, h2, r2); hilo(v.w, h3, r3);
        int w = r * S2 + (c4 >> 1);
        *(uint2*)&sAhi[w] = make_uint2(pack2(h0, h1), pack2(h2, h3));
        *(uint2*)&sAlo[w] = make_uint2(
            pack2(__float2half_rn(r0), __float2half_rn(r1)),
            pack2(__float2half_rn(r2), __float2half_rn(r3)));
    }
    // stage B [128 n x 32 kp]
#pragma unroll
    for (int it = 0; it < 2; it++) {
        int i = tid + it * 512;
        int n = i >> 3;
        int q = (i & 7) * 4;
        if (q < 32) {
            *(uint4*)&sBhi[n * S2 + q] = *(const uint4*)&Whi[n * 32 + q];
            *(uint4*)&sBlo[n * S2 + q] = *(const uint4*)&Wlo[n * 32 + q];
        }
    }
    __syncthreads();

#pragma unroll
    for (int ks = 0; ks < 4; ks++) {
        const int kb = ks * 8;
        uint32_t aH[2][4], aL[2][4];
#pragma unroll
        for (int mt = 0; mt < 2; mt++) {
            int base = (wm * 32 + mt * 16 + grp) * S2 + kb + tig;
            aH[mt][0] = sAhi[base];
            aH[mt][1] = sAhi[base + 8 * S2];
            aH[mt][2] = sAhi[base + 4];
            aH[mt][3] = sAhi[base + 8 * S2 + 4];
            aL[mt][0] = sAlo[base];
            aL[mt][1] = sAlo[base + 8 * S2];
            aL[mt][2] = sAlo[base + 4];
            aL[mt][3] = sAlo[base + 8 * S2 + 4];
        }
#pragma unroll
        for (int nt = 0; nt < 4; nt++) {
            int bb = (wn * 32 + nt * 8 + grp) * S2 + kb + tig;
            uint32_t bh0 = sBhi[bb], bh1 = sBhi[bb + 4];
            uint32_t bl0 = sBlo[bb], bl1 = sBlo[bb + 4];
#pragma unroll
            for (int mt = 0; mt < 2; mt++) {
                mma_f16(acc[mt][nt], aH[mt], bh0, bh1);
                mma_f16(acc[mt][nt], aH[mt], bl0, bl1);
                mma_f16(acc[mt][nt], aL[mt], bh0, bh1);
            }
        }
    }

#pragma unroll
    for (int mt = 0; mt < 2; mt++) {
        int ra = row0 + wm * 32 + mt * 16 + grp;
        int rb = ra + 8;
#pragma unroll
        for (int nt = 0; nt < 4; nt++) {
            int col = wn * 32 + nt * 8 + 2 * tig;
            float b0 = sBias[col], b1 = sBias[col + 1];
            __half2 pa2 = __floats2half2_rn(acc[mt][nt][0] + b0, acc[mt][nt][1] + b1);
            __half2 pb2 = __floats2half2_rn(acc[mt][nt][2] + b0, acc[mt][nt][3] + b1);
            if (ra < M) C16[(size_t)ra * 64 + (col >> 1)] = *(uint32_t*)&pa2;
            if (rb < M) C16[(size_t)rb * 64 + (col >> 1)] = *(uint32_t*)&pb2;
        }
    }
}
#define SM_EMBED (4 * TILEW * 4 + 128 * 4)

// ---------------- fused 2-layer MLP: xs = relu(relu(h@W1+b1)@W2+b2) * invs ----------------
// A tile (h, fp16) staged full-K; hidden tile overwrites A buffer between GEMMs.
__global__ __launch_bounds__(512, 2)
void k_mlp(const uint32_t* __restrict__ A16,
           const uint32_t* __restrict__ W1hi, const uint32_t* __restrict__ W1lo,
           const uint32_t* __restrict__ W2hi, const uint32_t* __restrict__ W2lo,
           const float* __restrict__ b1, const float* __restrict__ b2,
           uint32_t* __restrict__ C16, int M) {
    extern __shared__ uint32_t sm[];
    uint32_t* sA   = sm;                       // 128 x S2F (full K, fp16 words)
    uint32_t* sBhi = sm + 128 * S2F;           // chunk
    uint32_t* sBlo = sBhi + TILEW;
    float*    sB1  = (float*)(sBlo + TILEW);   // 128
    float*    sB2  = sB1 + 128;                // 128

    const int tid  = threadIdx.x;
    const int lane = tid & 31;
    const int wid  = tid >> 5;
    const int grp  = lane >> 2;
    const int tig  = lane & 3;
    const int wm   = wid & 3;
    const int wn   = wid >> 2;
    const int row0 = blockIdx.x * 128;

    if (tid < 128) { sB1[tid] = b1[tid]; sB2[tid] = b2[tid]; }

    // stage A full-K [128 rows x 64 words]
#pragma unroll
    for (int it = 0; it < 4; it++) {
        int i = tid + it * 512;              // 2048 uint4
        int r = i >> 4;
        int q = (i & 15) * 4;
        uint4 v = make_uint4(0, 0, 0, 0);
        if (row0 + r < M)
            v = *(const uint4*)&A16[(size_t)(row0 + r) * 64 + q];
        *(uint4*)&sA[r * S2F + q] = v;
    }

    float acc[2][4][4];
#pragma unroll
    for (int i = 0; i < 2; i++)
#pragma unroll
        for (int j = 0; j < 4; j++)
#pragma unroll
            for (int q = 0; q < 4; q++) acc[i][j][q] = 0.f;

    // ================= GEMM 1 =================
    for (int ch = 0; ch < 2; ch++) {
        if (ch) __syncthreads();
        // stage B1 chunk
#pragma unroll
        for (int it = 0; it < 2; it++) {
            int i = tid + it * 512;
            int n = i >> 3;
            int q = (i & 7) * 4;
            int gw = n * 64 + ch * 32 + q;
            *(uint4*)&sBhi[n * S2 + q] = *(const uint4*)&W1hi[gw];
            *(uint4*)&sBlo[n * S2 + q] = *(const uint4*)&W1lo[gw];
        }
        __syncthreads();
#pragma unroll
        for (int ks = 0; ks < 4; ks++) {
            const int kb = ks * 8;
            uint32_t aH[2][4];
#pragma unroll
            for (int mt = 0; mt < 2; mt++) {
                int base = (wm * 32 + mt * 16 + grp) * S2F + ch * 32 + kb + tig;
                aH[mt][0] = sA[base];
                aH[mt][1] = sA[base + 8 * S2F];
                aH[mt][2] = sA[base + 4];
                aH[mt][3] = sA[base + 8 * S2F + 4];
            }
#pragma unroll
            for (int nt = 0; nt < 4; nt++) {
                int bb = (wn * 32 + nt * 8 + grp) * S2 + kb + tig;
                uint32_t bh0 = sBhi[bb], bh1 = sBhi[bb + 4];
                uint32_t bl0 = sBlo[bb], bl1 = sBlo[bb + 4];
#pragma unroll
                for (int mt = 0; mt < 2; mt++) {
                    mma_f16(acc[mt][nt], aH[mt], bh0, bh1);
                    mma_f16(acc[mt][nt], aH[mt], bl0, bl1);
                }
            }
        }
    }
    __syncthreads();   // all GEMM1 reads of sA/sB done

    // hidden = relu(acc + b1) -> overwrite sA (local rows, packed half2)
#pragma unroll
    for (int mt = 0; mt < 2; mt++) {
        int lr = wm * 32 + mt * 16 + grp;
#pragma unroll
        for (int nt = 0; nt < 4; nt++) {
            int col = wn * 32 + nt * 8 + 2 * tig;
            float b0 = sB1[col], bq = sB1[col + 1];
            float v0 = fmaxf(acc[mt][nt][0] + b0, 0.f);
            float v1 = fmaxf(acc[mt][nt][1] + bq, 0.f);
            float v2 = fmaxf(acc[mt][nt][2] + b0, 0.f);
            float v3 = fmaxf(acc[mt][nt][3] + bq, 0.f);
            sA[lr * S2F + (col >> 1)]       = pack2(__float2half_rn(v0), __float2half_rn(v1));
            sA[(lr + 8) * S2F + (col >> 1)] = pack2(__float2half_rn(v2), __float2half_rn(v3));
            acc[mt][nt][0] = 0.f; acc[mt][nt][1] = 0.f;
            acc[mt][nt][2] = 0.f; acc[mt][nt][3] = 0.f;
        }
    }

    // ================= GEMM 2 =================
    for (int ch = 0; ch < 2; ch++) {
        if (ch) __syncthreads();
#pragma unroll
        for (int it = 0; it < 2; it++) {
            int i = tid + it * 512;
            int n = i >> 3;
            int q = (i & 7) * 4;
            int gw = n * 64 + ch * 32 + q;
            *(uint4*)&sBhi[n * S2 + q] = *(const uint4*)&W2hi[gw];
            *(uint4*)&sBlo[n * S2 + q] = *(const uint4*)&W2lo[gw];
        }
        __syncthreads();   // hidden writes + B2 staging visible
#pragma unroll
        for (int ks = 0; ks < 4; ks++) {
            const int kb = ks * 8;
            uint32_t aH[2][4];
#pragma unroll
            for (int mt = 0; mt < 2; mt++) {
                int base = (wm * 32 + mt * 16 + grp) * S2F + ch * 32 + kb + tig;
                aH[mt][0] = sA[base];
                aH[mt][1] = sA[base + 8 * S2F];
                aH[mt][2] = sA[base + 4];
                aH[mt][3] = sA[base + 8 * S2F + 4];
            }
#pragma unroll
            for (int nt = 0; nt < 4; nt++) {
                int bb = (wn * 32 + nt * 8 + grp) * S2 + kb + tig;
                uint32_t bh0 = sBhi[bb], bh1 = sBhi[bb + 4];
                uint32_t bl0 = sBlo[bb], bl1 = sBlo[bb + 4];
#pragma unroll
                for (int mt = 0; mt < 2; mt++) {
                    mma_f16(acc[mt][nt], aH[mt], bh0, bh1);
                    mma_f16(acc[mt][nt], aH[mt], bl0, bl1);
                }
            }
        }
    }

    // epilogue: relu(acc + b2) * invs -> xs16
#pragma unroll
    for (int mt = 0; mt < 2; mt++) {
        int ra = row0 + wm * 32 + mt * 16 + grp;
        int rb = ra + 8;
        float sa = (ra < M) ? g_invs[ra] : 0.f;
        float sb = (rb < M) ? g_invs[rb] : 0.f;
#pragma unroll
        for (int nt = 0; nt < 4; nt++) {
            int col = wn * 32 + nt * 8 + 2 * tig;
            float b0 = sB2[col], bq = sB2[col + 1];
            float v0 = fmaxf(acc[mt][nt][0] + b0, 0.f) * sa;
            float v1 = fmaxf(acc[mt][nt][1] + bq, 0.f) * sa;
            float v2 = fmaxf(acc[mt][nt][2] + b0, 0.f) * sb;
            float v3 = fmaxf(acc[mt][nt][3] + bq, 0.f) * sb;
            __half2 pa2 = __floats2half2_rn(v0, v1);
            __half2 pb2 = __floats2half2_rn(v2, v3);
            if (ra < M) C16[(size_t)ra * 64 + (col >> 1)] = *(uint32_t*)&pa2;
            if (rb < M) C16[(size_t)rb * 64 + (col >> 1)] = *(uint32_t*)&pb2;
        }
    }
}
#define SM_MLP ((128 * S2F + 2 * TILEW) * 4 + 256 * 4)   // ~72.7 KB

// ---------------- fused CSR gather (fp16) + skip + LayerNorm (fp16 h) ----------------
__global__ __launch_bounds__(256)
void k_gln(const uint32_t* __restrict__ xs16, uint32_t* __restrict__ h16,
           const float* __restrict__ scale, const float* __restrict__ offset) {
    int node = (blockIdx.x * blockDim.x + threadIdx.x) >> 5;
    int lane = threadIdx.x & 31;
    if (node >= N_NODES) return;
    const int c = lane * 4;
    const int w = lane * 2;

    float4 acc;
    {
        uint2 sv = *(const uint2*)&xs16[(size_t)node * 64 + w];
        float2 f0 = __half22float2(*(__half2*)&sv.x);
        float2 f1 = __half22float2(*(__half2*)&sv.y);
        acc = make_float4(f0.x, f0.y, f1.x, f1.y);
    }
    const int beg = g_start[node];
    const int end = beg + g_cr[node];

    for (int base = beg; base < end; base += 32) {
        int idx = (base + lane < end) ? g_csr[base + lane] : 0;
        int m = min(32, end - base);
        int j = 0;
        for (; j + 4 <= m; j += 4) {
            int s0 = __shfl_sync(0xffffffffu, idx, j);
            int s1 = __shfl_sync(0xffffffffu, idx, j + 1);
            int s2 = __shfl_sync(0xffffffffu, idx, j + 2);
            int s3 = __shfl_sync(0xffffffffu, idx, j + 3);
            uint2 v0 = *(const uint2*)&xs16[(size_t)s0 * 64 + w];
            uint2 v1 = *(const uint2*)&xs16[(size_t)s1 * 64 + w];
            uint2 v2 = *(const uint2*)&xs16[(size_t)s2 * 64 + w];
            uint2 v3 = *(const uint2*)&xs16[(size_t)s3 * 64 + w];
            float2 e;
            e = __half22float2(*(__half2*)&v0.x); acc.x += e.x; acc.y += e.y;
            e = __half22float2(*(__half2*)&v1.x); acc.x += e.x; acc.y += e.y;
            e = __half22float2(*(__half2*)&v2.x); acc.x += e.x; acc.y += e.y;
            e = __half22float2(*(__half2*)&v3.x); acc.x += e.x; acc.y += e.y;
            e = __half22float2(*(__half2*)&v0.y); acc.z += e.x; acc.w += e.y;
            e = __half22float2(*(__half2*)&v1.y); acc.z += e.x; acc.w += e.y;
            e = __half22float2(*(__half2*)&v2.y); acc.z += e.x; acc.w += e.y;
            e = __half22float2(*(__half2*)&v3.y); acc.z += e.x; acc.w += e.y;
        }
        for (; j < m; j++) {
            int s = __shfl_sync(0xffffffffu, idx, j);
            uint2 v = *(const uint2*)&xs16[(size_t)s * 64 + w];
            float2 f0 = __half22float2(*(__half2*)&v.x);
            float2 f1 = __half22float2(*(__half2*)&v.y);
            acc.x += f0.x; acc.y += f0.y; acc.z += f1.x; acc.w += f1.y;
        }
    }

    float ir = g_invr[node];
    float4 vh;
    {
        uint2 hv = *(const uint2*)&h16[(size_t)node * 64 + w];
        float2 f0 = __half22float2(*(__half2*)&hv.x);
        float2 f1 = __half22float2(*(__half2*)&hv.y);
        vh = make_float4(f0.x, f0.y, f1.x, f1.y);
    }
    float4 y;
    y.x = acc.x * ir + vh.x; y.y = acc.y * ir + vh.y;
    y.z = acc.z * ir + vh.z; y.w = acc.w * ir + vh.w;

    float sum = y.x + y.y + y.z + y.w;
    float sq  = y.x * y.x + y.y * y.y + y.z * y.z + y.w * y.w;
#pragma unroll
    for (int o = 16; o; o >>= 1) {
        sum += __shfl_xor_sync(0xffffffffu, sum, o);
        sq  += __shfl_xor_sync(0xffffffffu, sq, o);
    }
    float mean = sum * (1.f / 128.f);
    float var  = sq * (1.f / 128.f) - mean * mean;
    float rs = rsqrtf(var + LN_EPS);
    float4 scv = *(const float4*)&scale[c];
    float4 ofv = *(const float4*)&offset[c];
    y.x = (y.x - mean) * rs * scv.x + ofv.x;
    y.y = (y.y - mean) * rs * scv.y + ofv.y;
    y.z = (y.z - mean) * rs * scv.z + ofv.z;
    y.w = (y.w - mean) * rs * scv.w + ofv.w;
    __half2 p0 = __floats2half2_rn(y.x, y.y);
    __half2 p1 = __floats2half2_rn(y.z, y.w);
    *(uint2*)&h16[(size_t)node * 64 + w] = make_uint2(*(uint32_t*)&p0, *(uint32_t*)&p1);
}

// ---------------- pool (fp16 h) + decode ----------------
__global__ __launch_bounds__(64)
void k_pool(const uint32_t* __restrict__ h16, const float* __restrict__ dec_w,
            const float* __restrict__ dec_b, float* __restrict__ out) {
    int g = blockIdx.x;
    int w = threadIdx.x;
    const int per = N_NODES / N_GRAPH;
    const uint32_t* base = h16 + (size_t)g * per * 64;
    float s0 = 0.f, s1 = 0.f;
#pragma unroll 8
    for (int r = 0; r < per; r++) {
        uint32_t v = base[(size_t)r * 64 + w];
        float2 f = __half22float2(*(__half2*)&v);
        s0 += f.x; s1 += f.y;
    }
    float val = (s0 * dec_w[2 * w] + s1 * dec_w[2 * w + 1]) * (1.f / (float)per);
    __shared__ float red[2];
#pragma unroll
    for (int o = 16; o; o >>= 1) val += __shfl_xor_sync(0xffffffffu, val, o);
    if ((threadIdx.x & 31) == 0) red[threadIdx.x >> 5] = val;
    __syncthreads();
    if (threadIdx.x == 0) out[g] = red[0] + red[1] + dec_b[0];
}

// ---------------- launch ----------------
extern "C" void kernel_launch(void* const* d_in, const int* in_sizes, int n_in,
                              void* d_out, int out_size) {
    const float* nodes     = (const float*)d_in[0];
    const int*   senders   = (const int*)d_in[1];
    const int*   receivers = (const int*)d_in[2];
    const float* embed_w   = (const float*)d_in[4];
    const float* embed_b   = (const float*)d_in[5];
    const float* mlp_w     = (const float*)d_in[6];
    const float* mlp_b     = (const float*)d_in[7];
    const float* ln_scale  = (const float*)d_in[8];
    const float* ln_offset = (const float*)d_in[9];
    const float* dec_w     = (const float*)d_in[10];
    const float* dec_b     = (const float*)d_in[11];
    float* out = (float*)d_out;

    uint32_t *ph16, *px16, *pwhi, *pwlo;
    cudaGetSymbolAddress((void**)&ph16, g_h16);
    cudaGetSymbolAddress((void**)&px16, g_x16);
    cudaGetSymbolAddress((void**)&pwhi, g_whi);
    cudaGetSymbolAddress((void**)&pwlo, g_wlo);

    cudaFuncSetAttribute(k_embed, cudaFuncAttributeMaxDynamicSharedMemorySize, SM_EMBED);
    cudaFuncSetAttribute(k_mlp,   cudaFuncAttributeMaxDynamicSharedMemorySize, SM_MLP);

    static cudaStream_t s2 = nullptr;
    static cudaEvent_t evFork = nullptr, evInv = nullptr, evJoin = nullptr;
    if (!s2) {
        cudaStreamCreateWithFlags(&s2, cudaStreamNonBlocking);
        cudaEventCreateWithFlags(&evFork, cudaEventDisableTiming);
        cudaEventCreateWithFlags(&evInv, cudaEventDisableTiming);
        cudaEventCreateWithFlags(&evJoin, cudaEventDisableTiming);
    }

    // ---- fork: CSR build on s2 ----
    cudaEventRecord(evFork, 0);
    cudaStreamWaitEvent(s2, evFork, 0);
    k_zero_deg<<<(N_NODES + 255) / 256, 256, 0, s2>>>();
    k_count<<<(N_EDGES + 255) / 256, 256, 0, s2>>>(senders, receivers);
    k_inv<<<(N_NODES + 255) / 256, 256, 0, s2>>>();
    cudaEventRecord(evInv, s2);        // invs/invr/start ready
    k_fill<<<(N_EDGES + 255) / 256, 256, 0, s2>>>(senders, receivers);
    cudaEventRecord(evJoin, s2);       // CSR fully ready

    const int gemm_grid = (N_NODES + 127) / 128;

    k_wconv<<<(WCONV_WORDS + 255) / 256, 256>>>(embed_w, mlp_w);
    k_embed<<<gemm_grid, 512, SM_EMBED>>>(nodes, pwhi, pwlo, embed_b, ph16, N_NODES);

    const uint32_t* whi_mlp[4];
    const uint32_t* wlo_mlp[4];
    for (int g = 0; g < 4; g++) {
        whi_mlp[g] = pwhi + 4096 + g * 8192;
        wlo_mlp[g] = pwlo + 4096 + g * 8192;
    }

    const int row_grid = (N_NODES * 32 + 255) / 256;

    cudaStreamWaitEvent(0, evInv, 0);      // epilogue of k_mlp needs g_invs

    for (int s = 0; s < 2; s++) {
        const float* b0 = mlp_b + (size_t)(s * 2 + 0) * LATENT;
        const float* b1 = mlp_b + (size_t)(s * 2 + 1) * LATENT;

        // xs = relu(relu(h@W0+b0)@W1+b1) * inv_sqrt_sdeg   (fused 2-layer MLP)
        k_mlp<<<gemm_grid, 512, SM_MLP>>>(ph16,
                                          whi_mlp[s * 2], wlo_mlp[s * 2],
                                          whi_mlp[s * 2 + 1], wlo_mlp[s * 2 + 1],
                                          b0, b1, px16, N_NODES);
        if (s == 0) cudaStreamWaitEvent(0, evJoin, 0);   // k_gln needs full CSR
        // h = LN((xs[self] + sum_in xs) * inv_sqrt_rdeg + h)
        k_gln<<<row_grid, 256>>>(px16, ph16, ln_scale + s * LATENT, ln_offset + s * LATENT);
    }

    k_pool<<<N_GRAPH, 64>>>(ph16, dec_w, dec_b, out);
}